// round 2
// baseline (speedup 1.0000x reference)
#include <cuda_runtime.h>
#include <math.h>

#define NP 16384
#define BB 4

static constexpr size_t F1 = (size_t)BB * 128 * NP;  // one 128-channel map: 8,388,608 floats

static constexpr size_t OFF_XN   = 0;
static constexpr size_t OFF_YN   = F1;        // reused for z = ln(xatt) later
static constexpr size_t OFF_B1   = 2 * F1;    // q pre-dw
static constexpr size_t OFF_Q    = 3 * F1;
static constexpr size_t OFF_KVP  = 4 * F1;    // 2*F1
static constexpr size_t OFF_KV   = 6 * F1;    // 2*F1
static constexpr size_t OFF_OUT  = 8 * F1;    // attn @ v
static constexpr size_t OFF_XATT = 9 * F1;
static constexpr size_t OFF_TPRE = 10 * F1;                       // 680ch
static constexpr size_t OFF_T    = OFF_TPRE + (size_t)BB*680*NP;  // 680ch
static constexpr size_t OFF_X12  = OFF_T    + (size_t)BB*680*NP;  // 340ch
static constexpr size_t OFF_G1   = OFF_X12  + (size_t)BB*340*NP;  // 64ch
static constexpr size_t OFF_ATTN = OFF_G1   + (size_t)BB*64*NP;   // 4*8*16*16
static constexpr size_t OFF_QSS  = OFF_ATTN + 8192;               // 512
static constexpr size_t OFF_KSS  = OFF_QSS  + 512;                // 512
static constexpr size_t OFF_PART = OFF_KSS  + 512;                // 256 partials
static constexpr size_t SCRATCH_TOTAL = OFF_PART + 256;

__device__ float g_scratch[SCRATCH_TOTAL];
__device__ int   g_dk;

// ---------------- LayerNorm over channel axis (C=128), NCHW ----------------
__global__ void ln_kernel(const float* __restrict__ in_ptr, size_t in_off, size_t out_off,
                          const float* __restrict__ w, const float* __restrict__ bp)
{
    int p = blockIdx.x * blockDim.x + threadIdx.x;   // pixel within batch
    int b = blockIdx.y;
    const float* ip = (in_ptr ? in_ptr : g_scratch + in_off) + (size_t)b * 128 * NP + p;
    float s = 0.f, ss = 0.f;
    #pragma unroll 8
    for (int c = 0; c < 128; c++) { float v = ip[(size_t)c * NP]; s += v; ss += v * v; }
    float mu  = s * (1.f / 128.f);
    float var = ss * (1.f / 128.f) - mu * mu;
    float inv = rsqrtf(var + 1e-6f);
    float* op = g_scratch + out_off + (size_t)b * 128 * NP + p;
    #pragma unroll 8
    for (int c = 0; c < 128; c++) {
        float v = ip[(size_t)c * NP];
        op[(size_t)c * NP] = w[c] * ((v - mu) * inv) + bp[c];
    }
}

// ---------------- 1x1 conv as per-batch GEMM: out[M,NP] = W[M,K] @ in[K,NP] --
// rflag: 0 = none, 1 = residual from resid_ptr, 2 = residual from scratch+resid_off
__global__ void gemm1x1(const float* __restrict__ W, size_t in_off,
                        float* __restrict__ out_ptr, size_t out_off,
                        int M, int K,
                        const float* __restrict__ bias, int do_relu,
                        const float* __restrict__ resid_ptr, size_t resid_off, int rflag)
{
    __shared__ float As[16][64];
    __shared__ float Bs[16][64];
    int b = blockIdx.z;
    const float* in = g_scratch + in_off + (size_t)b * K * NP;
    float* out = (out_ptr ? out_ptr : g_scratch + out_off) + (size_t)b * M * NP;
    const float* res = nullptr;
    if (rflag == 1)      res = resid_ptr + (size_t)b * M * NP;
    else if (rflag == 2) res = g_scratch + resid_off + (size_t)b * M * NP;

    int m0 = blockIdx.y * 64, n0 = blockIdx.x * 64;
    int t = threadIdx.x;
    int tx = t & 15, ty = t >> 4;
    float acc[4][4] = {};

    for (int k0 = 0; k0 < K; k0 += 16) {
        #pragma unroll
        for (int i = 0; i < 4; i++) {
            int idx = t + i * 256;               // 0..1023
            int mm = idx >> 4, kk = idx & 15;
            float wv = 0.f;
            int m = m0 + mm, k = k0 + kk;
            if (m < M && k < K) wv = W[(size_t)m * K + k];
            As[kk][mm] = wv;
            int kk2 = idx >> 6, nn = idx & 63;
            float iv = 0.f;
            if (k0 + kk2 < K) iv = in[(size_t)(k0 + kk2) * NP + n0 + nn];
            Bs[kk2][nn] = iv;
        }
        __syncthreads();
        #pragma unroll
        for (int kk = 0; kk < 16; kk++) {
            float a[4], bb[4];
            #pragma unroll
            for (int i = 0; i < 4; i++) a[i]  = As[kk][ty * 4 + i];
            #pragma unroll
            for (int j = 0; j < 4; j++) bb[j] = Bs[kk][tx * 4 + j];
            #pragma unroll
            for (int i = 0; i < 4; i++)
                #pragma unroll
                for (int j = 0; j < 4; j++)
                    acc[i][j] += a[i] * bb[j];
        }
        __syncthreads();
    }

    #pragma unroll
    for (int i = 0; i < 4; i++) {
        int m = m0 + ty * 4 + i;
        if (m >= M) break;
        float bv = bias ? bias[m] : 0.f;
        #pragma unroll
        for (int j = 0; j < 4; j++) {
            int n = n0 + tx * 4 + j;
            float v = acc[i][j] + bv;
            if (do_relu) v = fmaxf(v, 0.f);
            if (res) v += res[(size_t)m * NP + n];
            out[(size_t)m * NP + n] = v;
        }
    }
}

// ---------------- depthwise 3x3, pad=1, no bias ----------------
__global__ void dwconv3x3(size_t in_off, size_t out_off, const float* __restrict__ wts, int C)
{
    size_t idx = (size_t)blockIdx.x * blockDim.x + threadIdx.x;
    size_t total = (size_t)BB * C * NP;
    if (idx >= total) return;
    int wpos = (int)(idx & 127);
    int hpos = (int)((idx >> 7) & 127);
    int c = (int)((idx / NP) % C);
    const float* ip = g_scratch + in_off + (idx - (idx & (NP - 1)));   // channel plane base
    const float* kp = wts + c * 9;
    float acc = 0.f;
    #pragma unroll
    for (int dy = -1; dy <= 1; dy++) {
        int hy = hpos + dy;
        if ((unsigned)hy >= 128u) continue;
        #pragma unroll
        for (int dx = -1; dx <= 1; dx++) {
            int wx = wpos + dx;
            if ((unsigned)wx >= 128u) continue;
            acc += kp[(dy + 1) * 3 + dx + 1] * ip[hy * 128 + wx];
        }
    }
    g_scratch[out_off + idx] = acc;
}

// ---------------- per-channel sum of squares (for q/k L2 norms) ----------------
__global__ void chan_sumsq(size_t in_off, size_t out_off, int Cstride)
{
    int c = blockIdx.x;   // 0..127
    int b = blockIdx.y;
    const float* ip = g_scratch + in_off + ((size_t)b * Cstride + c) * NP;
    float s = 0.f;
    for (int i = threadIdx.x; i < NP; i += 256) { float v = ip[i]; s += v * v; }
    __shared__ float red[256];
    red[threadIdx.x] = s; __syncthreads();
    for (int st = 128; st; st >>= 1) {
        if (threadIdx.x < st) red[threadIdx.x] += red[threadIdx.x + st];
        __syncthreads();
    }
    if (!threadIdx.x) g_scratch[out_off + b * 128 + c] = red[0];
}

// ---------------- attention logits: 16x16 per (b,h), K=16384, scaled ----------
__global__ void qk_attn(const float* __restrict__ temp)
{
    int b = blockIdx.y, h = blockIdx.x;
    int t = threadIdx.x;
    int c = t >> 4, d = t & 15;
    const float4* qp = (const float4*)(g_scratch + OFF_Q  + ((size_t)b * 128 + h * 16 + c) * NP);
    const float4* kp = (const float4*)(g_scratch + OFF_KV + ((size_t)b * 256 + h * 16 + d) * NP);
    float a0 = 0.f, a1 = 0.f, a2 = 0.f, a3 = 0.f;
    #pragma unroll 4
    for (int n = 0; n < NP / 4; n++) {
        float4 qv = qp[n]; float4 kv = kp[n];
        a0 += qv.x * kv.x; a1 += qv.y * kv.y; a2 += qv.z * kv.z; a3 += qv.w * kv.w;
    }
    float acc = (a0 + a1) + (a2 + a3);
    float qn = fmaxf(sqrtf(g_scratch[OFF_QSS + b * 128 + h * 16 + c]), 1e-12f);
    float kn = fmaxf(sqrtf(g_scratch[OFF_KSS + b * 128 + h * 16 + d]), 1e-12f);
    g_scratch[OFF_ATTN + ((size_t)(b * 8 + h) * 16 + c) * 16 + d] = acc / (qn * kn) * temp[h];
}

// ---------------- dynamic top-k mask + softmax (rank = stable desc argsort) ---
__global__ void mask_softmax()
{
    int r = blockIdx.x * blockDim.x + threadIdx.x;   // 512 rows total
    if (r >= BB * 8 * 16) return;
    float* row = g_scratch + OFF_ATTN + (size_t)r * 16;
    int dk = g_dk;
    float vals[16];
    #pragma unroll
    for (int i = 0; i < 16; i++) vals[i] = row[i];
    float mx = -3.4e38f;
    bool keep[16];
    #pragma unroll
    for (int i = 0; i < 16; i++) {
        int rank = 0;
        #pragma unroll
        for (int j = 0; j < 16; j++)
            rank += (vals[j] > vals[i]) || (vals[j] == vals[i] && j < i);
        keep[i] = rank < dk;
        if (keep[i] && vals[i] > mx) mx = vals[i];
    }
    float sum = 0.f, e[16];
    #pragma unroll
    for (int i = 0; i < 16; i++) { e[i] = keep[i] ? expf(vals[i] - mx) : 0.f; sum += e[i]; }
    float isum = 1.f / sum;
    #pragma unroll
    for (int i = 0; i < 16; i++) row[i] = e[i] * isum;
}

// ---------------- out = attn @ v ----------------
__global__ void av_kernel()
{
    int b = blockIdx.z, h = blockIdx.y;
    int n = blockIdx.x * 256 + threadIdx.x;
    __shared__ float at[256];
    at[threadIdx.x] = g_scratch[OFF_ATTN + (size_t)(b * 8 + h) * 256 + threadIdx.x];
    __syncthreads();
    float v[16];
    const float* vp = g_scratch + OFF_KV + ((size_t)b * 256 + 128 + h * 16) * NP + n;
    #pragma unroll
    for (int d = 0; d < 16; d++) v[d] = vp[(size_t)d * NP];
    float* op = g_scratch + OFF_OUT + ((size_t)b * 128 + h * 16) * NP + n;
    #pragma unroll
    for (int c = 0; c < 16; c++) {
        float acc = 0.f;
        #pragma unroll
        for (int d = 0; d < 16; d++) acc += at[c * 16 + d] * v[d];
        op[(size_t)c * NP] = acc;
    }
}

// ---------------- gate: g2 conv + sigmoid + deterministic partial sums --------
__global__ void gate_reduce(const float* __restrict__ g2w, const float* __restrict__ g2b)
{
    int p = blockIdx.x * blockDim.x + threadIdx.x;   // 0..65535
    int b = p / NP, pp = p % NP;
    const float* base = g_scratch + OFF_G1 + ((size_t)b * 64) * NP + pp;
    float s = g2b[0];
    #pragma unroll 8
    for (int c = 0; c < 64; c++) s += g2w[c] * base[(size_t)c * NP];
    float v = 1.f / (1.f + expf(-s));
    __shared__ float red[256];
    red[threadIdx.x] = v; __syncthreads();
    for (int st = 128; st; st >>= 1) {
        if (threadIdx.x < st) red[threadIdx.x] += red[threadIdx.x + st];
        __syncthreads();
    }
    if (!threadIdx.x) g_scratch[OFF_PART + blockIdx.x] = red[0];
}

__global__ void finish_gate()
{
    __shared__ float red[256];
    red[threadIdx.x] = g_scratch[OFF_PART + threadIdx.x];
    __syncthreads();
    for (int st = 128; st; st >>= 1) {
        if (threadIdx.x < st) red[threadIdx.x] += red[threadIdx.x + st];
        __syncthreads();
    }
    if (!threadIdx.x) {
        float mean = red[0] * (1.f / 65536.f);
        int dk = (int)(16.f * mean);               // trunc like astype(int32)
        g_dk = dk < 1 ? 1 : (dk > 16 ? 16 : dk);
    }
}

// ---------------- IEL tail: x12 = (tanh(dw1(x1))+x1) * (tanh(dw2(x2))+x2) -----
__global__ void iel_fuse(const float* __restrict__ w1, const float* __restrict__ w2)
{
    size_t idx = (size_t)blockIdx.x * blockDim.x + threadIdx.x;
    if (idx >= (size_t)BB * 340 * NP) return;
    int wpos = (int)(idx & 127);
    int hpos = (int)((idx >> 7) & 127);
    int c = (int)((idx / NP) % 340);
    int b = (int)(idx / ((size_t)340 * NP));
    const float* p1 = g_scratch + OFF_T + ((size_t)b * 680 + c) * NP;
    const float* p2 = p1 + (size_t)340 * NP;
    const float* k1 = w1 + c * 9;
    const float* k2 = w2 + c * 9;
    float a1 = 0.f, a2 = 0.f;
    #pragma unroll
    for (int dy = -1; dy <= 1; dy++) {
        int hy = hpos + dy;
        if ((unsigned)hy >= 128u) continue;
        #pragma unroll
        for (int dx = -1; dx <= 1; dx++) {
            int wx = wpos + dx;
            if ((unsigned)wx >= 128u) continue;
            int off = hy * 128 + wx;
            int widx = (dy + 1) * 3 + (dx + 1);
            a1 += k1[widx] * p1[off];
            a2 += k2[widx] * p2[off];
        }
    }
    int pix = hpos * 128 + wpos;
    float r1 = tanhf(a1) + p1[pix];
    float r2 = tanhf(a2) + p2[pix];
    g_scratch[OFF_X12 + ((size_t)b * 340 + c) * NP + pix] = r1 * r2;
}

// ============================================================================
extern "C" void kernel_launch(void* const* d_in, const int* in_sizes, int n_in,
                              void* d_out, int out_size)
{
    const float* x      = (const float*)d_in[0];
    const float* y      = (const float*)d_in[1];
    const float* ln_w   = (const float*)d_in[2];
    const float* ln_b   = (const float*)d_in[3];
    const float* temp   = (const float*)d_in[4];
    const float* q_w    = (const float*)d_in[5];
    const float* qdw_w  = (const float*)d_in[6];
    const float* kv_w   = (const float*)d_in[7];
    const float* kvdw_w = (const float*)d_in[8];
    const float* po_w   = (const float*)d_in[9];
    const float* g1_w   = (const float*)d_in[10];
    const float* g1_b   = (const float*)d_in[11];
    const float* g2_w   = (const float*)d_in[12];
    const float* g2_b   = (const float*)d_in[13];
    const float* pin_w  = (const float*)d_in[14];
    const float* dw_w   = (const float*)d_in[15];
    const float* dw1_w  = (const float*)d_in[16];
    const float* dw2_w  = (const float*)d_in[17];
    const float* pout_w = (const float*)d_in[18];
    float* out = (float*)d_out;

    dim3 lnGrid(NP / 256, BB);
    ln_kernel<<<lnGrid, 256>>>(x, 0, OFF_XN, ln_w, ln_b);
    ln_kernel<<<lnGrid, 256>>>(y, 0, OFF_YN, ln_w, ln_b);

    // SCAB branch
    dim3 gg128(NP / 64, 2, BB);
    gemm1x1<<<gg128, 256>>>(q_w, OFF_XN, nullptr, OFF_B1, 128, 128, nullptr, 0, nullptr, 0, 0);
    {
        size_t tot = (size_t)BB * 128 * NP;
        dwconv3x3<<<(unsigned)((tot + 255) / 256), 256>>>(OFF_B1, OFF_Q, qdw_w, 128);
    }
    dim3 gg256(NP / 64, 4, BB);
    gemm1x1<<<gg256, 256>>>(kv_w, OFF_YN, nullptr, OFF_KVP, 256, 128, nullptr, 0, nullptr, 0, 0);
    {
        size_t tot = (size_t)BB * 256 * NP;
        dwconv3x3<<<(unsigned)((tot + 255) / 256), 256>>>(OFF_KVP, OFF_KV, kvdw_w, 256);
    }

    dim3 cs(128, BB);
    chan_sumsq<<<cs, 256>>>(OFF_Q,  OFF_QSS, 128);
    chan_sumsq<<<cs, 256>>>(OFF_KV, OFF_KSS, 256);

    // gate -> dk
    dim3 gg64(NP / 64, 1, BB);
    gemm1x1<<<gg64, 256>>>(g1_w, OFF_XN, nullptr, OFF_G1, 64, 128, g1_b, 1, nullptr, 0, 0);
    gate_reduce<<<256, 256>>>(g2_w, g2_b);
    finish_gate<<<1, 256>>>();

    // attention
    qk_attn<<<dim3(8, BB), 256>>>(temp);
    mask_softmax<<<2, 256>>>();
    av_kernel<<<dim3(NP / 256, 8, BB), 256>>>();

    // xatt = x + conv1x1(out, po_w)
    gemm1x1<<<gg128, 256>>>(po_w, OFF_OUT, nullptr, OFF_XATT, 128, 128, nullptr, 0, x, 0, 1);

    // IEL branch
    ln_kernel<<<lnGrid, 256>>>(nullptr, OFF_XATT, OFF_YN, ln_w, ln_b);
    dim3 gg680(NP / 64, 11, BB);
    gemm1x1<<<gg680, 256>>>(pin_w, OFF_YN, nullptr, OFF_TPRE, 680, 128, nullptr, 0, nullptr, 0, 0);
    {
        size_t tot = (size_t)BB * 680 * NP;
        dwconv3x3<<<(unsigned)((tot + 255) / 256), 256>>>(OFF_TPRE, OFF_T, dw_w, 680);
    }
    {
        size_t tot = (size_t)BB * 340 * NP;
        iel_fuse<<<(unsigned)((tot + 255) / 256), 256>>>(dw1_w, dw2_w);
    }
    // final: out = conv1x1(x12, pout_w) + xatt
    gemm1x1<<<gg128, 256>>>(pout_w, OFF_X12, out, 0, 128, 340, nullptr, 0, nullptr, OFF_XATT, 2);
}

// round 3
// speedup vs baseline: 2.4524x; 2.4524x over previous
#include <cuda_runtime.h>
#include <math.h>

#define NP 16384
#define BB 4

static constexpr size_t F1 = (size_t)BB * 128 * NP;  // 8,388,608 floats

static constexpr size_t OFF_XN   = 0;
static constexpr size_t OFF_YN   = F1;        // reused for z = ln(xatt) later
static constexpr size_t OFF_B1   = 2 * F1;    // q pre-dw
static constexpr size_t OFF_Q    = 3 * F1;
static constexpr size_t OFF_KVP  = 4 * F1;    // 2*F1
static constexpr size_t OFF_KV   = 6 * F1;    // 2*F1
static constexpr size_t OFF_OUT  = 8 * F1;    // attn @ v
static constexpr size_t OFF_XATT = 9 * F1;
static constexpr size_t OFF_TPRE = 10 * F1;                       // 680ch
static constexpr size_t OFF_T    = OFF_TPRE + (size_t)BB*680*NP;  // 680ch
static constexpr size_t OFF_X12  = OFF_T    + (size_t)BB*680*NP;  // 340ch
static constexpr size_t OFF_G1   = OFF_X12  + (size_t)BB*340*NP;  // 64ch
static constexpr size_t OFF_ATTN = OFF_G1   + (size_t)BB*64*NP;   // 4*8*16*16
static constexpr size_t OFF_QSS  = OFF_ATTN + 8192;               // 512
static constexpr size_t OFF_KSS  = OFF_QSS  + 512;                // 512
static constexpr size_t OFF_PART = OFF_KSS  + 512;                // 256 partials
static constexpr size_t OFF_QKP  = OFF_PART + 256;                // 32*64*256 qk partials
static constexpr size_t SCRATCH_TOTAL = OFF_QKP + (size_t)32 * 64 * 256;

__device__ float g_scratch[SCRATCH_TOTAL];
__device__ int   g_dk;

// ---------------- LayerNorm over channel axis (C=128), NCHW ----------------
__global__ void ln_kernel(const float* __restrict__ in_ptr, size_t in_off, size_t out_off,
                          const float* __restrict__ w, const float* __restrict__ bp)
{
    int p = blockIdx.x * blockDim.x + threadIdx.x;   // pixel within batch
    int b = blockIdx.y;
    const float* ip = (in_ptr ? in_ptr : g_scratch + in_off) + (size_t)b * 128 * NP + p;
    float s = 0.f, ss = 0.f;
    #pragma unroll 8
    for (int c = 0; c < 128; c++) { float v = ip[(size_t)c * NP]; s += v; ss += v * v; }
    float mu  = s * (1.f / 128.f);
    float var = ss * (1.f / 128.f) - mu * mu;
    float inv = rsqrtf(var + 1e-6f);
    float* op = g_scratch + out_off + (size_t)b * 128 * NP + p;
    #pragma unroll 8
    for (int c = 0; c < 128; c++) {
        float v = ip[(size_t)c * NP];
        op[(size_t)c * NP] = w[c] * ((v - mu) * inv) + bp[c];
    }
}

// ---------------- 1x1 conv GEMM v2: 128x128 tile, 8x8/thread, float4 ----------
// out[M,NP] = W[M,K] @ in[K,NP] per batch. rflag: 0 none, 1 resid ptr, 2 resid scratch
__global__ __launch_bounds__(256, 2)
void gemm1x1(const float* __restrict__ W, size_t in_off,
             float* __restrict__ out_ptr, size_t out_off,
             int M, int K,
             const float* __restrict__ bias, int do_relu,
             const float* __restrict__ resid_ptr, size_t resid_off, int rflag)
{
    __shared__ float As[16][132];
    __shared__ float Bs[16][132];
    int b = blockIdx.z;
    const float* in = g_scratch + in_off + (size_t)b * K * NP;
    float* out = (out_ptr ? out_ptr : g_scratch + out_off) + (size_t)b * M * NP;
    const float* res = nullptr;
    if (rflag == 1)      res = resid_ptr + (size_t)b * M * NP;
    else if (rflag == 2) res = g_scratch + resid_off + (size_t)b * M * NP;

    int m0 = blockIdx.y * 128, n0 = blockIdx.x * 128;
    int t = threadIdx.x;
    int tx = t & 15, ty = t >> 4;
    float acc[8][8] = {};

    int KT = (K + 15) >> 4;
    for (int kt = 0; kt < KT; kt++) {
        int k0 = kt << 4;
        // load A tile: 128 rows x 16 k, as 2 float4 per thread along K
        #pragma unroll
        for (int i = 0; i < 2; i++) {
            int idx = t * 2 + i;                  // 0..511
            int row = idx >> 2, seg = idx & 3;
            int m = m0 + row, k = k0 + seg * 4;
            float4 w4 = make_float4(0.f, 0.f, 0.f, 0.f);
            if (m < M && k < K) w4 = *(const float4*)&W[(size_t)m * K + k];
            As[seg * 4 + 0][row] = w4.x;
            As[seg * 4 + 1][row] = w4.y;
            As[seg * 4 + 2][row] = w4.z;
            As[seg * 4 + 3][row] = w4.w;
        }
        // load B tile: 16 k x 128 n, as 2 float4 per thread along n
        #pragma unroll
        for (int i = 0; i < 2; i++) {
            int idx = t * 2 + i;                  // 0..511
            int kk = idx >> 5, seg = idx & 31;
            float4 v4 = make_float4(0.f, 0.f, 0.f, 0.f);
            if (k0 + kk < K) v4 = *(const float4*)&in[(size_t)(k0 + kk) * NP + n0 + seg * 4];
            *(float4*)&Bs[kk][seg * 4] = v4;
        }
        __syncthreads();
        #pragma unroll
        for (int kk = 0; kk < 16; kk++) {
            float4 a0 = *(float4*)&As[kk][ty * 8];
            float4 a1 = *(float4*)&As[kk][ty * 8 + 4];
            float4 b0 = *(float4*)&Bs[kk][tx * 8];
            float4 b1 = *(float4*)&Bs[kk][tx * 8 + 4];
            float a[8] = {a0.x, a0.y, a0.z, a0.w, a1.x, a1.y, a1.z, a1.w};
            float bbv[8] = {b0.x, b0.y, b0.z, b0.w, b1.x, b1.y, b1.z, b1.w};
            #pragma unroll
            for (int i = 0; i < 8; i++)
                #pragma unroll
                for (int j = 0; j < 8; j++)
                    acc[i][j] += a[i] * bbv[j];
        }
        __syncthreads();
    }

    #pragma unroll
    for (int i = 0; i < 8; i++) {
        int m = m0 + ty * 8 + i;
        if (m >= M) break;
        float bv = bias ? bias[m] : 0.f;
        size_t rowoff = (size_t)m * NP + n0 + tx * 8;
        float v[8];
        #pragma unroll
        for (int j = 0; j < 8; j++) {
            v[j] = acc[i][j] + bv;
            if (do_relu) v[j] = fmaxf(v[j], 0.f);
        }
        if (res) {
            float4 r0 = *(const float4*)&res[rowoff];
            float4 r1 = *(const float4*)&res[rowoff + 4];
            v[0] += r0.x; v[1] += r0.y; v[2] += r0.z; v[3] += r0.w;
            v[4] += r1.x; v[5] += r1.y; v[6] += r1.z; v[7] += r1.w;
        }
        *(float4*)&out[rowoff]     = make_float4(v[0], v[1], v[2], v[3]);
        *(float4*)&out[rowoff + 4] = make_float4(v[4], v[5], v[6], v[7]);
    }
}

// ---------------- tiled depthwise 3x3, pad=1 ----------------
__global__ void dwconv_tiled(size_t in_off, size_t out_off, const float* __restrict__ wts, int C)
{
    __shared__ float tile[18][130];
    int plane = blockIdx.x;                 // b*C + c
    int c = plane % C;
    int r0 = blockIdx.y * 16;
    int x = threadIdx.x;                    // 0..127
    const float* ip = g_scratch + in_off + (size_t)plane * NP;
    float* op = g_scratch + out_off + (size_t)plane * NP;

    #pragma unroll
    for (int i = 0; i < 18; i++) {
        int y = r0 - 1 + i;
        tile[i][x + 1] = ((unsigned)y < 128u) ? ip[y * 128 + x] : 0.f;
    }
    if (x < 18) { tile[x][0] = 0.f; tile[x][129] = 0.f; }
    __syncthreads();

    const float* kp = wts + c * 9;
    float w00 = kp[0], w01 = kp[1], w02 = kp[2];
    float w10 = kp[3], w11 = kp[4], w12 = kp[5];
    float w20 = kp[6], w21 = kp[7], w22 = kp[8];

    float a0 = tile[0][x], a1 = tile[0][x + 1], a2 = tile[0][x + 2];
    float b0 = tile[1][x], b1 = tile[1][x + 1], b2 = tile[1][x + 2];
    #pragma unroll
    for (int i = 0; i < 16; i++) {
        float c0 = tile[i + 2][x], c1 = tile[i + 2][x + 1], c2 = tile[i + 2][x + 2];
        float acc = w00 * a0 + w01 * a1 + w02 * a2
                  + w10 * b0 + w11 * b1 + w12 * b2
                  + w20 * c0 + w21 * c1 + w22 * c2;
        op[(r0 + i) * 128 + x] = acc;
        a0 = b0; a1 = b1; a2 = b2;
        b0 = c0; b1 = c1; b2 = c2;
    }
}

// ---------------- per-channel sum of squares ----------------
__global__ void chan_sumsq(size_t in_off, size_t out_off, int Cstride)
{
    int c = blockIdx.x;
    int b = blockIdx.y;
    const float4* ip = (const float4*)(g_scratch + in_off + ((size_t)b * Cstride + c) * NP);
    float s = 0.f;
    for (int i = threadIdx.x; i < NP / 4; i += 256) {
        float4 v = ip[i];
        s += v.x * v.x + v.y * v.y + v.z * v.z + v.w * v.w;
    }
    __shared__ float red[256];
    red[threadIdx.x] = s; __syncthreads();
    for (int st = 128; st; st >>= 1) {
        if (threadIdx.x < st) red[threadIdx.x] += red[threadIdx.x + st];
        __syncthreads();
    }
    if (!threadIdx.x) g_scratch[out_off + b * 128 + c] = red[0];
}

// ---------------- qk partials: 16x16 over a 256-px chunk per block ------------
__global__ void qk_partial()
{
    __shared__ float qs[16][257];
    __shared__ float ks[16][257];
    int chunk = blockIdx.x, h = blockIdx.y, b = blockIdx.z;
    int n0 = chunk * 256;
    int t = threadIdx.x;
    const float* qbase = g_scratch + OFF_Q  + ((size_t)b * 128 + h * 16) * NP + n0;
    const float* kbase = g_scratch + OFF_KV + ((size_t)b * 256 + h * 16) * NP + n0;
    #pragma unroll
    for (int r = 0; r < 16; r++) {
        qs[r][t] = qbase[(size_t)r * NP + t];
        ks[r][t] = kbase[(size_t)r * NP + t];
    }
    __syncthreads();
    int c = t >> 4, d = t & 15;
    float acc = 0.f;
    #pragma unroll 8
    for (int n = 0; n < 256; n++) acc += qs[c][n] * ks[d][n];
    g_scratch[OFF_QKP + (((size_t)(b * 8 + h) * 64 + chunk) * 256) + t] = acc;
}

// ---------------- qk reduce + normalize + temperature -------------------------
__global__ void qk_reduce(const float* __restrict__ temp)
{
    int h = blockIdx.x, b = blockIdx.y;
    int t = threadIdx.x;
    float acc = 0.f;
    const float* p = g_scratch + OFF_QKP + (size_t)(b * 8 + h) * 64 * 256 + t;
    #pragma unroll 8
    for (int j = 0; j < 64; j++) acc += p[j * 256];
    int c = t >> 4, d = t & 15;
    float qn = fmaxf(sqrtf(g_scratch[OFF_QSS + b * 128 + h * 16 + c]), 1e-12f);
    float kn = fmaxf(sqrtf(g_scratch[OFF_KSS + b * 128 + h * 16 + d]), 1e-12f);
    g_scratch[OFF_ATTN + (size_t)(b * 8 + h) * 256 + t] = acc / (qn * kn) * temp[h];
}

// ---------------- dynamic top-k mask + softmax --------------------------------
__global__ void mask_softmax()
{
    int r = blockIdx.x * blockDim.x + threadIdx.x;   // 512 rows total
    if (r >= BB * 8 * 16) return;
    float* row = g_scratch + OFF_ATTN + (size_t)r * 16;
    int dk = g_dk;
    float vals[16];
    #pragma unroll
    for (int i = 0; i < 16; i++) vals[i] = row[i];
    float mx = -3.4e38f;
    bool keep[16];
    #pragma unroll
    for (int i = 0; i < 16; i++) {
        int rank = 0;
        #pragma unroll
        for (int j = 0; j < 16; j++)
            rank += (vals[j] > vals[i]) || (vals[j] == vals[i] && j < i);
        keep[i] = rank < dk;
        if (keep[i] && vals[i] > mx) mx = vals[i];
    }
    float sum = 0.f, e[16];
    #pragma unroll
    for (int i = 0; i < 16; i++) { e[i] = keep[i] ? expf(vals[i] - mx) : 0.f; sum += e[i]; }
    float isum = 1.f / sum;
    #pragma unroll
    for (int i = 0; i < 16; i++) row[i] = e[i] * isum;
}

// ---------------- out = attn @ v ----------------
__global__ void av_kernel()
{
    int b = blockIdx.z, h = blockIdx.y;
    int n = blockIdx.x * 256 + threadIdx.x;
    __shared__ float at[256];
    at[threadIdx.x] = g_scratch[OFF_ATTN + (size_t)(b * 8 + h) * 256 + threadIdx.x];
    __syncthreads();
    float v[16];
    const float* vp = g_scratch + OFF_KV + ((size_t)b * 256 + 128 + h * 16) * NP + n;
    #pragma unroll
    for (int d = 0; d < 16; d++) v[d] = vp[(size_t)d * NP];
    float* op = g_scratch + OFF_OUT + ((size_t)b * 128 + h * 16) * NP + n;
    #pragma unroll
    for (int c = 0; c < 16; c++) {
        float acc = 0.f;
        #pragma unroll
        for (int d = 0; d < 16; d++) acc += at[c * 16 + d] * v[d];
        op[(size_t)c * NP] = acc;
    }
}

// ---------------- gate: g2 conv + sigmoid + deterministic partial sums --------
__global__ void gate_reduce(const float* __restrict__ g2w, const float* __restrict__ g2b)
{
    int p = blockIdx.x * blockDim.x + threadIdx.x;   // 0..65535
    int b = p / NP, pp = p % NP;
    const float* base = g_scratch + OFF_G1 + ((size_t)b * 64) * NP + pp;
    float s = g2b[0];
    #pragma unroll 8
    for (int c = 0; c < 64; c++) s += g2w[c] * base[(size_t)c * NP];
    float v = 1.f / (1.f + expf(-s));
    __shared__ float red[256];
    red[threadIdx.x] = v; __syncthreads();
    for (int st = 128; st; st >>= 1) {
        if (threadIdx.x < st) red[threadIdx.x] += red[threadIdx.x + st];
        __syncthreads();
    }
    if (!threadIdx.x) g_scratch[OFF_PART + blockIdx.x] = red[0];
}

__global__ void finish_gate()
{
    __shared__ float red[256];
    red[threadIdx.x] = g_scratch[OFF_PART + threadIdx.x];
    __syncthreads();
    for (int st = 128; st; st >>= 1) {
        if (threadIdx.x < st) red[threadIdx.x] += red[threadIdx.x + st];
        __syncthreads();
    }
    if (!threadIdx.x) {
        float mean = red[0] * (1.f / 65536.f);
        int dk = (int)(16.f * mean);               // trunc like astype(int32)
        g_dk = dk < 1 ? 1 : (dk > 16 ? 16 : dk);
    }
}

// ---------------- IEL tail (tiled): x12 = (tanh(dw1(x1))+x1)*(tanh(dw2(x2))+x2)
__global__ void iel_tiled(const float* __restrict__ w1, const float* __restrict__ w2)
{
    __shared__ float t1[18][130];
    __shared__ float t2[18][130];
    int pid = blockIdx.x;                  // b*340 + c
    int b = pid / 340, c = pid % 340;
    int r0 = blockIdx.y * 16;
    int x = threadIdx.x;
    const float* p1 = g_scratch + OFF_T + ((size_t)b * 680 + c) * NP;
    const float* p2 = p1 + (size_t)340 * NP;

    #pragma unroll
    for (int i = 0; i < 18; i++) {
        int y = r0 - 1 + i;
        bool ok = (unsigned)y < 128u;
        t1[i][x + 1] = ok ? p1[y * 128 + x] : 0.f;
        t2[i][x + 1] = ok ? p2[y * 128 + x] : 0.f;
    }
    if (x < 18) { t1[x][0] = 0.f; t1[x][129] = 0.f; t2[x][0] = 0.f; t2[x][129] = 0.f; }
    __syncthreads();

    const float* k1 = w1 + c * 9;
    const float* k2 = w2 + c * 9;
    float u00 = k1[0], u01 = k1[1], u02 = k1[2], u10 = k1[3], u11 = k1[4],
          u12 = k1[5], u20 = k1[6], u21 = k1[7], u22 = k1[8];
    float v00 = k2[0], v01 = k2[1], v02 = k2[2], v10 = k2[3], v11 = k2[4],
          v12 = k2[5], v20 = k2[6], v21 = k2[7], v22 = k2[8];

    float a10 = t1[0][x], a11 = t1[0][x + 1], a12 = t1[0][x + 2];
    float b10 = t1[1][x], b11 = t1[1][x + 1], b12 = t1[1][x + 2];
    float a20 = t2[0][x], a21 = t2[0][x + 1], a22 = t2[0][x + 2];
    float b20 = t2[1][x], b21 = t2[1][x + 1], b22 = t2[1][x + 2];

    float* op = g_scratch + OFF_X12 + ((size_t)b * 340 + c) * NP;
    #pragma unroll
    for (int i = 0; i < 16; i++) {
        float c10 = t1[i + 2][x], c11 = t1[i + 2][x + 1], c12 = t1[i + 2][x + 2];
        float c20 = t2[i + 2][x], c21 = t2[i + 2][x + 1], c22 = t2[i + 2][x + 2];
        float acc1 = u00 * a10 + u01 * a11 + u02 * a12
                   + u10 * b10 + u11 * b11 + u12 * b12
                   + u20 * c10 + u21 * c11 + u22 * c12;
        float acc2 = v00 * a20 + v01 * a21 + v02 * a22
                   + v10 * b20 + v11 * b21 + v12 * b22
                   + v20 * c20 + v21 * c21 + v22 * c22;
        float r1 = tanhf(acc1) + b11;
        float r2 = tanhf(acc2) + b21;
        op[(r0 + i) * 128 + x] = r1 * r2;
        a10 = b10; a11 = b11; a12 = b12; b10 = c10; b11 = c11; b12 = c12;
        a20 = b20; a21 = b21; a22 = b22; b20 = c20; b21 = c21; b22 = c22;
    }
}

// ============================================================================
extern "C" void kernel_launch(void* const* d_in, const int* in_sizes, int n_in,
                              void* d_out, int out_size)
{
    const float* x      = (const float*)d_in[0];
    const float* y      = (const float*)d_in[1];
    const float* ln_w   = (const float*)d_in[2];
    const float* ln_b   = (const float*)d_in[3];
    const float* temp   = (const float*)d_in[4];
    const float* q_w    = (const float*)d_in[5];
    const float* qdw_w  = (const float*)d_in[6];
    const float* kv_w   = (const float*)d_in[7];
    const float* kvdw_w = (const float*)d_in[8];
    const float* po_w   = (const float*)d_in[9];
    const float* g1_w   = (const float*)d_in[10];
    const float* g1_b   = (const float*)d_in[11];
    const float* g2_w   = (const float*)d_in[12];
    const float* g2_b   = (const float*)d_in[13];
    const float* pin_w  = (const float*)d_in[14];
    const float* dw_w   = (const float*)d_in[15];
    const float* dw1_w  = (const float*)d_in[16];
    const float* dw2_w  = (const float*)d_in[17];
    const float* pout_w = (const float*)d_in[18];
    float* out = (float*)d_out;

    dim3 lnGrid(NP / 256, BB);
    ln_kernel<<<lnGrid, 256>>>(x, 0, OFF_XN, ln_w, ln_b);
    ln_kernel<<<lnGrid, 256>>>(y, 0, OFF_YN, ln_w, ln_b);

    // SCAB branch
    dim3 gg128(NP / 128, 1, BB);
    gemm1x1<<<gg128, 256>>>(q_w, OFF_XN, nullptr, OFF_B1, 128, 128, nullptr, 0, nullptr, 0, 0);
    dwconv_tiled<<<dim3(BB * 128, 8), 128>>>(OFF_B1, OFF_Q, qdw_w, 128);

    dim3 gg256(NP / 128, 2, BB);
    gemm1x1<<<gg256, 256>>>(kv_w, OFF_YN, nullptr, OFF_KVP, 256, 128, nullptr, 0, nullptr, 0, 0);
    dwconv_tiled<<<dim3(BB * 256, 8), 128>>>(OFF_KVP, OFF_KV, kvdw_w, 256);

    dim3 cs(128, BB);
    chan_sumsq<<<cs, 256>>>(OFF_Q,  OFF_QSS, 128);
    chan_sumsq<<<cs, 256>>>(OFF_KV, OFF_KSS, 256);

    // gate -> dk
    gemm1x1<<<gg128, 256>>>(g1_w, OFF_XN, nullptr, OFF_G1, 64, 128, g1_b, 1, nullptr, 0, 0);
    gate_reduce<<<256, 256>>>(g2_w, g2_b);
    finish_gate<<<1, 256>>>();

    // attention
    qk_partial<<<dim3(64, 8, BB), 256>>>();
    qk_reduce<<<dim3(8, BB), 256>>>(temp);
    mask_softmax<<<2, 256>>>();
    av_kernel<<<dim3(NP / 256, 8, BB), 256>>>();

    // xatt = x + conv1x1(out, po_w)
    gemm1x1<<<gg128, 256>>>(po_w, OFF_OUT, nullptr, OFF_XATT, 128, 128, nullptr, 0, x, 0, 1);

    // IEL branch
    ln_kernel<<<lnGrid, 256>>>(nullptr, OFF_XATT, OFF_YN, ln_w, ln_b);
    dim3 gg680(NP / 128, 6, BB);
    gemm1x1<<<gg680, 256>>>(pin_w, OFF_YN, nullptr, OFF_TPRE, 680, 128, nullptr, 0, nullptr, 0, 0);
    dwconv_tiled<<<dim3(BB * 680, 8), 128>>>(OFF_TPRE, OFF_T, dw_w, 680);
    iel_tiled<<<dim3(BB * 340, 8), 128>>>(dw1_w, dw2_w);

    // final: out = conv1x1(x12, pout_w) + xatt
    gemm1x1<<<gg128, 256>>>(pout_w, OFF_X12, out, 0, 128, 340, nullptr, 0, nullptr, OFF_XATT, 2);
}

// round 4
// speedup vs baseline: 3.7822x; 1.5423x over previous
#include <cuda_runtime.h>
#include <math.h>

#define NP 16384
#define BB 4

static constexpr size_t F1 = (size_t)BB * 128 * NP;  // 8,388,608 floats

static constexpr size_t OFF_XN   = 0;
static constexpr size_t OFF_YN   = F1;        // reused for z = ln(xatt) later
static constexpr size_t OFF_B1   = 2 * F1;    // q pre-dw
static constexpr size_t OFF_Q    = 3 * F1;
static constexpr size_t OFF_KVP  = 4 * F1;    // 2*F1
static constexpr size_t OFF_KV   = 6 * F1;    // 2*F1
static constexpr size_t OFF_OUT  = 8 * F1;    // attn @ v
static constexpr size_t OFF_XATT = 9 * F1;
static constexpr size_t OFF_TPRE = 10 * F1;                       // 680ch
static constexpr size_t OFF_T    = OFF_TPRE + (size_t)BB*680*NP;  // 680ch
static constexpr size_t OFF_X12  = OFF_T    + (size_t)BB*680*NP;  // 340ch
static constexpr size_t OFF_G1   = OFF_X12  + (size_t)BB*340*NP;  // 64ch
static constexpr size_t OFF_ATTN = OFF_G1   + (size_t)BB*64*NP;   // 4*8*16*16
static constexpr size_t OFF_QSS  = OFF_ATTN + 8192;               // 512
static constexpr size_t OFF_KSS  = OFF_QSS  + 512;                // 512
static constexpr size_t OFF_PART = OFF_KSS  + 512;                // 256 partials
static constexpr size_t OFF_QKP  = OFF_PART + 256;                // 32*64*256 qk partials
static constexpr size_t SCRATCH_TOTAL = OFF_QKP + (size_t)32 * 64 * 256;

__device__ float g_scratch[SCRATCH_TOTAL];
__device__ int   g_dk;

__device__ __forceinline__ unsigned f2tf32(float f) {
    unsigned r;
    asm("cvt.rna.tf32.f32 %0, %1;" : "=r"(r) : "f"(f));
    return r;
}

// ---------------- LayerNorm over channel axis (C=128), NCHW ----------------
__global__ void ln_kernel(const float* __restrict__ in_ptr, size_t in_off, size_t out_off,
                          const float* __restrict__ w, const float* __restrict__ bp)
{
    int p = blockIdx.x * blockDim.x + threadIdx.x;   // pixel within batch
    int b = blockIdx.y;
    const float* ip = (in_ptr ? in_ptr : g_scratch + in_off) + (size_t)b * 128 * NP + p;
    float s = 0.f, ss = 0.f;
    #pragma unroll 8
    for (int c = 0; c < 128; c++) { float v = ip[(size_t)c * NP]; s += v; ss += v * v; }
    float mu  = s * (1.f / 128.f);
    float var = ss * (1.f / 128.f) - mu * mu;
    float inv = rsqrtf(var + 1e-6f);
    float* op = g_scratch + out_off + (size_t)b * 128 * NP + p;
    #pragma unroll 8
    for (int c = 0; c < 128; c++) {
        float v = ip[(size_t)c * NP];
        op[(size_t)c * NP] = w[c] * ((v - mu) * inv) + bp[c];
    }
}

// ---------------- tf32 tensor-core GEMM: out[M,NP] = W[M,K] @ in[K,NP] --------
// 128x128 block tile, 8 warps (2x4), 64x32 warp tile, m16n8k8 tf32 mma.
// rflag: 0 none, 1 residual from resid_ptr, 2 residual from scratch+resid_off
__global__ __launch_bounds__(256, 2)
void gemm_tf32(const float* __restrict__ W, size_t in_off,
               float* __restrict__ out_ptr, size_t out_off,
               int M, int K,
               const float* __restrict__ resid_ptr, size_t resid_off, int rflag)
{
    __shared__ unsigned As[32][136];   // [k][m] tf32 bits
    __shared__ unsigned Bs[32][136];   // [k][n] tf32 bits

    int b = blockIdx.z;
    const float* in = g_scratch + in_off + (size_t)b * K * NP;
    float* out = (out_ptr ? out_ptr : g_scratch + out_off) + (size_t)b * M * NP;
    const float* res = nullptr;
    if (rflag == 1)      res = resid_ptr + (size_t)b * M * NP;
    else if (rflag == 2) res = g_scratch + resid_off + (size_t)b * M * NP;

    int m0 = blockIdx.y * 128, n0 = blockIdx.x * 128;
    int t = threadIdx.x;
    int lane = t & 31, wid = t >> 5;
    int wm = (wid & 1) * 64;        // warp m offset in tile
    int wn = (wid >> 1) * 32;       // warp n offset in tile
    int gid = lane >> 2, tig = lane & 3;

    float acc[4][4][4];
    #pragma unroll
    for (int i = 0; i < 4; i++)
        #pragma unroll
        for (int j = 0; j < 4; j++)
            #pragma unroll
            for (int r = 0; r < 4; r++) acc[i][j][r] = 0.f;

    int KT = (K + 31) >> 5;
    for (int kt = 0; kt < KT; kt++) {
        int k0 = kt << 5;
        // ---- load A tile: As[k][m] <- W[m0+m][k0+k], tf32 ----
        #pragma unroll
        for (int i = 0; i < 4; i++) {
            int lin = t + i * 256;            // 0..1023
            int m = lin >> 3, kq = lin & 7;   // m 0..127, kq 0..7 (4 k each)
            int gm = m0 + m, gk = k0 + kq * 4;
            float v0 = 0.f, v1 = 0.f, v2 = 0.f, v3 = 0.f;
            if (gm < M) {
                if (gk + 3 < K) {
                    float4 w4 = *(const float4*)&W[(size_t)gm * K + gk];
                    v0 = w4.x; v1 = w4.y; v2 = w4.z; v3 = w4.w;
                } else {
                    if (gk + 0 < K) v0 = W[(size_t)gm * K + gk + 0];
                    if (gk + 1 < K) v1 = W[(size_t)gm * K + gk + 1];
                    if (gk + 2 < K) v2 = W[(size_t)gm * K + gk + 2];
                    if (gk + 3 < K) v3 = W[(size_t)gm * K + gk + 3];
                }
            }
            As[kq * 4 + 0][m] = f2tf32(v0);
            As[kq * 4 + 1][m] = f2tf32(v1);
            As[kq * 4 + 2][m] = f2tf32(v2);
            As[kq * 4 + 3][m] = f2tf32(v3);
        }
        // ---- load B tile: Bs[k][n] <- in[k0+k][n0+n], tf32 ----
        #pragma unroll
        for (int i = 0; i < 4; i++) {
            int lin = t + i * 256;            // 0..1023
            int kk = lin >> 5, nq = lin & 31; // kk 0..31, nq 0..31 (4 n each)
            unsigned u0 = 0, u1 = 0, u2 = 0, u3 = 0;
            if (k0 + kk < K) {
                float4 v4 = *(const float4*)&in[(size_t)(k0 + kk) * NP + n0 + nq * 4];
                u0 = f2tf32(v4.x); u1 = f2tf32(v4.y); u2 = f2tf32(v4.z); u3 = f2tf32(v4.w);
            }
            Bs[kk][nq * 4 + 0] = u0;
            Bs[kk][nq * 4 + 1] = u1;
            Bs[kk][nq * 4 + 2] = u2;
            Bs[kk][nq * 4 + 3] = u3;
        }
        __syncthreads();

        #pragma unroll
        for (int ks = 0; ks < 4; ks++) {
            int kb = ks * 8;
            unsigned af[4][4], bf[4][2];
            #pragma unroll
            for (int mi = 0; mi < 4; mi++) {
                int rlo = wm + mi * 16 + gid;
                af[mi][0] = As[kb + tig][rlo];
                af[mi][1] = As[kb + tig][rlo + 8];
                af[mi][2] = As[kb + tig + 4][rlo];
                af[mi][3] = As[kb + tig + 4][rlo + 8];
            }
            #pragma unroll
            for (int ni = 0; ni < 4; ni++) {
                int col = wn + ni * 8 + gid;
                bf[ni][0] = Bs[kb + tig][col];
                bf[ni][1] = Bs[kb + tig + 4][col];
            }
            #pragma unroll
            for (int mi = 0; mi < 4; mi++)
                #pragma unroll
                for (int ni = 0; ni < 4; ni++) {
                    asm volatile(
                        "mma.sync.aligned.m16n8k8.row.col.f32.tf32.tf32.f32 "
                        "{%0,%1,%2,%3}, {%4,%5,%6,%7}, {%8,%9}, {%0,%1,%2,%3};"
                        : "+f"(acc[mi][ni][0]), "+f"(acc[mi][ni][1]),
                          "+f"(acc[mi][ni][2]), "+f"(acc[mi][ni][3])
                        : "r"(af[mi][0]), "r"(af[mi][1]), "r"(af[mi][2]), "r"(af[mi][3]),
                          "r"(bf[ni][0]), "r"(bf[ni][1]));
                }
        }
        __syncthreads();
    }

    // ---- epilogue ----
    #pragma unroll
    for (int mi = 0; mi < 4; mi++) {
        int row0 = m0 + wm + mi * 16 + gid;
        int row1 = row0 + 8;
        #pragma unroll
        for (int ni = 0; ni < 4; ni++) {
            int col = n0 + wn + ni * 8 + tig * 2;
            if (row0 < M) {
                float2 v = make_float2(acc[mi][ni][0], acc[mi][ni][1]);
                if (res) {
                    float2 r = *(const float2*)&res[(size_t)row0 * NP + col];
                    v.x += r.x; v.y += r.y;
                }
                *(float2*)&out[(size_t)row0 * NP + col] = v;
            }
            if (row1 < M) {
                float2 v = make_float2(acc[mi][ni][2], acc[mi][ni][3]);
                if (res) {
                    float2 r = *(const float2*)&res[(size_t)row1 * NP + col];
                    v.x += r.x; v.y += r.y;
                }
                *(float2*)&out[(size_t)row1 * NP + col] = v;
            }
        }
    }
}

// ---------------- fp32 GEMM (gate path only — dk must stay bit-stable) -------
__global__ __launch_bounds__(256, 2)
void gemm1x1(const float* __restrict__ W, size_t in_off,
             float* __restrict__ out_ptr, size_t out_off,
             int M, int K,
             const float* __restrict__ bias, int do_relu)
{
    __shared__ float As[16][132];
    __shared__ float Bs[16][132];
    int b = blockIdx.z;
    const float* in = g_scratch + in_off + (size_t)b * K * NP;
    float* out = (out_ptr ? out_ptr : g_scratch + out_off) + (size_t)b * M * NP;

    int m0 = blockIdx.y * 128, n0 = blockIdx.x * 128;
    int t = threadIdx.x;
    int tx = t & 15, ty = t >> 4;
    float acc[8][8] = {};

    int KT = (K + 15) >> 4;
    for (int kt = 0; kt < KT; kt++) {
        int k0 = kt << 4;
        #pragma unroll
        for (int i = 0; i < 2; i++) {
            int idx = t * 2 + i;
            int row = idx >> 2, seg = idx & 3;
            int m = m0 + row, k = k0 + seg * 4;
            float4 w4 = make_float4(0.f, 0.f, 0.f, 0.f);
            if (m < M && k < K) w4 = *(const float4*)&W[(size_t)m * K + k];
            As[seg * 4 + 0][row] = w4.x;
            As[seg * 4 + 1][row] = w4.y;
            As[seg * 4 + 2][row] = w4.z;
            As[seg * 4 + 3][row] = w4.w;
        }
        #pragma unroll
        for (int i = 0; i < 2; i++) {
            int idx = t * 2 + i;
            int kk = idx >> 5, seg = idx & 31;
            float4 v4 = make_float4(0.f, 0.f, 0.f, 0.f);
            if (k0 + kk < K) v4 = *(const float4*)&in[(size_t)(k0 + kk) * NP + n0 + seg * 4];
            *(float4*)&Bs[kk][seg * 4] = v4;
        }
        __syncthreads();
        #pragma unroll
        for (int kk = 0; kk < 16; kk++) {
            float4 a0 = *(float4*)&As[kk][ty * 8];
            float4 a1 = *(float4*)&As[kk][ty * 8 + 4];
            float4 b0 = *(float4*)&Bs[kk][tx * 8];
            float4 b1 = *(float4*)&Bs[kk][tx * 8 + 4];
            float a[8] = {a0.x, a0.y, a0.z, a0.w, a1.x, a1.y, a1.z, a1.w};
            float bbv[8] = {b0.x, b0.y, b0.z, b0.w, b1.x, b1.y, b1.z, b1.w};
            #pragma unroll
            for (int i = 0; i < 8; i++)
                #pragma unroll
                for (int j = 0; j < 8; j++)
                    acc[i][j] += a[i] * bbv[j];
        }
        __syncthreads();
    }

    #pragma unroll
    for (int i = 0; i < 8; i++) {
        int m = m0 + ty * 8 + i;
        if (m >= M) break;
        float bv = bias ? bias[m] : 0.f;
        size_t rowoff = (size_t)m * NP + n0 + tx * 8;
        float v[8];
        #pragma unroll
        for (int j = 0; j < 8; j++) {
            v[j] = acc[i][j] + bv;
            if (do_relu) v[j] = fmaxf(v[j], 0.f);
        }
        *(float4*)&out[rowoff]     = make_float4(v[0], v[1], v[2], v[3]);
        *(float4*)&out[rowoff + 4] = make_float4(v[4], v[5], v[6], v[7]);
    }
}

// ---------------- tiled depthwise 3x3, pad=1 ----------------
__global__ void dwconv_tiled(size_t in_off, size_t out_off, const float* __restrict__ wts, int C)
{
    __shared__ float tile[18][130];
    int plane = blockIdx.x;                 // b*C + c
    int c = plane % C;
    int r0 = blockIdx.y * 16;
    int x = threadIdx.x;                    // 0..127
    const float* ip = g_scratch + in_off + (size_t)plane * NP;
    float* op = g_scratch + out_off + (size_t)plane * NP;

    #pragma unroll
    for (int i = 0; i < 18; i++) {
        int y = r0 - 1 + i;
        tile[i][x + 1] = ((unsigned)y < 128u) ? ip[y * 128 + x] : 0.f;
    }
    if (x < 18) { tile[x][0] = 0.f; tile[x][129] = 0.f; }
    __syncthreads();

    const float* kp = wts + c * 9;
    float w00 = kp[0], w01 = kp[1], w02 = kp[2];
    float w10 = kp[3], w11 = kp[4], w12 = kp[5];
    float w20 = kp[6], w21 = kp[7], w22 = kp[8];

    float a0 = tile[0][x], a1 = tile[0][x + 1], a2 = tile[0][x + 2];
    float b0 = tile[1][x], b1 = tile[1][x + 1], b2 = tile[1][x + 2];
    #pragma unroll
    for (int i = 0; i < 16; i++) {
        float c0 = tile[i + 2][x], c1 = tile[i + 2][x + 1], c2 = tile[i + 2][x + 2];
        float acc = w00 * a0 + w01 * a1 + w02 * a2
                  + w10 * b0 + w11 * b1 + w12 * b2
                  + w20 * c0 + w21 * c1 + w22 * c2;
        op[(r0 + i) * 128 + x] = acc;
        a0 = b0; a1 = b1; a2 = b2;
        b0 = c0; b1 = c1; b2 = c2;
    }
}

// ---------------- per-channel sum of squares ----------------
__global__ void chan_sumsq(size_t in_off, size_t out_off, int Cstride)
{
    int c = blockIdx.x;
    int b = blockIdx.y;
    const float4* ip = (const float4*)(g_scratch + in_off + ((size_t)b * Cstride + c) * NP);
    float s = 0.f;
    for (int i = threadIdx.x; i < NP / 4; i += 256) {
        float4 v = ip[i];
        s += v.x * v.x + v.y * v.y + v.z * v.z + v.w * v.w;
    }
    __shared__ float red[256];
    red[threadIdx.x] = s; __syncthreads();
    for (int st = 128; st; st >>= 1) {
        if (threadIdx.x < st) red[threadIdx.x] += red[threadIdx.x + st];
        __syncthreads();
    }
    if (!threadIdx.x) g_scratch[out_off + b * 128 + c] = red[0];
}

// ---------------- qk partials: 16x16 over a 256-px chunk per block ------------
__global__ void qk_partial()
{
    __shared__ float qs[16][257];
    __shared__ float ks[16][257];
    int chunk = blockIdx.x, h = blockIdx.y, b = blockIdx.z;
    int n0 = chunk * 256;
    int t = threadIdx.x;
    const float* qbase = g_scratch + OFF_Q  + ((size_t)b * 128 + h * 16) * NP + n0;
    const float* kbase = g_scratch + OFF_KV + ((size_t)b * 256 + h * 16) * NP + n0;
    #pragma unroll
    for (int r = 0; r < 16; r++) {
        qs[r][t] = qbase[(size_t)r * NP + t];
        ks[r][t] = kbase[(size_t)r * NP + t];
    }
    __syncthreads();
    int c = t >> 4, d = t & 15;
    float acc = 0.f;
    #pragma unroll 8
    for (int n = 0; n < 256; n++) acc += qs[c][n] * ks[d][n];
    g_scratch[OFF_QKP + (((size_t)(b * 8 + h) * 64 + chunk) * 256) + t] = acc;
}

// ---------------- qk reduce + normalize + temperature -------------------------
__global__ void qk_reduce(const float* __restrict__ temp)
{
    int h = blockIdx.x, b = blockIdx.y;
    int t = threadIdx.x;
    float acc = 0.f;
    const float* p = g_scratch + OFF_QKP + (size_t)(b * 8 + h) * 64 * 256 + t;
    #pragma unroll 8
    for (int j = 0; j < 64; j++) acc += p[j * 256];
    int c = t >> 4, d = t & 15;
    float qn = fmaxf(sqrtf(g_scratch[OFF_QSS + b * 128 + h * 16 + c]), 1e-12f);
    float kn = fmaxf(sqrtf(g_scratch[OFF_KSS + b * 128 + h * 16 + d]), 1e-12f);
    g_scratch[OFF_ATTN + (size_t)(b * 8 + h) * 256 + t] = acc / (qn * kn) * temp[h];
}

// ---------------- dynamic top-k mask + softmax --------------------------------
__global__ void mask_softmax()
{
    int r = blockIdx.x * blockDim.x + threadIdx.x;   // 512 rows total
    if (r >= BB * 8 * 16) return;
    float* row = g_scratch + OFF_ATTN + (size_t)r * 16;
    int dk = g_dk;
    float vals[16];
    #pragma unroll
    for (int i = 0; i < 16; i++) vals[i] = row[i];
    float mx = -3.4e38f;
    bool keep[16];
    #pragma unroll
    for (int i = 0; i < 16; i++) {
        int rank = 0;
        #pragma unroll
        for (int j = 0; j < 16; j++)
            rank += (vals[j] > vals[i]) || (vals[j] == vals[i] && j < i);
        keep[i] = rank < dk;
        if (keep[i] && vals[i] > mx) mx = vals[i];
    }
    float sum = 0.f, e[16];
    #pragma unroll
    for (int i = 0; i < 16; i++) { e[i] = keep[i] ? expf(vals[i] - mx) : 0.f; sum += e[i]; }
    float isum = 1.f / sum;
    #pragma unroll
    for (int i = 0; i < 16; i++) row[i] = e[i] * isum;
}

// ---------------- out = attn @ v ----------------
__global__ void av_kernel()
{
    int b = blockIdx.z, h = blockIdx.y;
    int n = blockIdx.x * 256 + threadIdx.x;
    __shared__ float at[256];
    at[threadIdx.x] = g_scratch[OFF_ATTN + (size_t)(b * 8 + h) * 256 + threadIdx.x];
    __syncthreads();
    float v[16];
    const float* vp = g_scratch + OFF_KV + ((size_t)b * 256 + 128 + h * 16) * NP + n;
    #pragma unroll
    for (int d = 0; d < 16; d++) v[d] = vp[(size_t)d * NP];
    float* op = g_scratch + OFF_OUT + ((size_t)b * 128 + h * 16) * NP + n;
    #pragma unroll
    for (int c = 0; c < 16; c++) {
        float acc = 0.f;
        #pragma unroll
        for (int d = 0; d < 16; d++) acc += at[c * 16 + d] * v[d];
        op[(size_t)c * NP] = acc;
    }
}

// ---------------- gate: g2 conv + sigmoid + deterministic partial sums --------
__global__ void gate_reduce(const float* __restrict__ g2w, const float* __restrict__ g2b)
{
    int p = blockIdx.x * blockDim.x + threadIdx.x;   // 0..65535
    int b = p / NP, pp = p % NP;
    const float* base = g_scratch + OFF_G1 + ((size_t)b * 64) * NP + pp;
    float s = g2b[0];
    #pragma unroll 8
    for (int c = 0; c < 64; c++) s += g2w[c] * base[(size_t)c * NP];
    float v = 1.f / (1.f + expf(-s));
    __shared__ float red[256];
    red[threadIdx.x] = v; __syncthreads();
    for (int st = 128; st; st >>= 1) {
        if (threadIdx.x < st) red[threadIdx.x] += red[threadIdx.x + st];
        __syncthreads();
    }
    if (!threadIdx.x) g_scratch[OFF_PART + blockIdx.x] = red[0];
}

__global__ void finish_gate()
{
    __shared__ float red[256];
    red[threadIdx.x] = g_scratch[OFF_PART + threadIdx.x];
    __syncthreads();
    for (int st = 128; st; st >>= 1) {
        if (threadIdx.x < st) red[threadIdx.x] += red[threadIdx.x + st];
        __syncthreads();
    }
    if (!threadIdx.x) {
        float mean = red[0] * (1.f / 65536.f);
        int dk = (int)(16.f * mean);               // trunc like astype(int32)
        g_dk = dk < 1 ? 1 : (dk > 16 ? 16 : dk);
    }
}

// ---------------- IEL tail (tiled): x12 = (tanh(dw1(x1))+x1)*(tanh(dw2(x2))+x2)
__global__ void iel_tiled(const float* __restrict__ w1, const float* __restrict__ w2)
{
    __shared__ float t1[18][130];
    __shared__ float t2[18][130];
    int pid = blockIdx.x;                  // b*340 + c
    int b = pid / 340, c = pid % 340;
    int r0 = blockIdx.y * 16;
    int x = threadIdx.x;
    const float* p1 = g_scratch + OFF_T + ((size_t)b * 680 + c) * NP;
    const float* p2 = p1 + (size_t)340 * NP;

    #pragma unroll
    for (int i = 0; i < 18; i++) {
        int y = r0 - 1 + i;
        bool ok = (unsigned)y < 128u;
        t1[i][x + 1] = ok ? p1[y * 128 + x] : 0.f;
        t2[i][x + 1] = ok ? p2[y * 128 + x] : 0.f;
    }
    if (x < 18) { t1[x][0] = 0.f; t1[x][129] = 0.f; t2[x][0] = 0.f; t2[x][129] = 0.f; }
    __syncthreads();

    const float* k1 = w1 + c * 9;
    const float* k2 = w2 + c * 9;
    float u00 = k1[0], u01 = k1[1], u02 = k1[2], u10 = k1[3], u11 = k1[4],
          u12 = k1[5], u20 = k1[6], u21 = k1[7], u22 = k1[8];
    float v00 = k2[0], v01 = k2[1], v02 = k2[2], v10 = k2[3], v11 = k2[4],
          v12 = k2[5], v20 = k2[6], v21 = k2[7], v22 = k2[8];

    float a10 = t1[0][x], a11 = t1[0][x + 1], a12 = t1[0][x + 2];
    float b10 = t1[1][x], b11 = t1[1][x + 1], b12 = t1[1][x + 2];
    float a20 = t2[0][x], a21 = t2[0][x + 1], a22 = t2[0][x + 2];
    float b20 = t2[1][x], b21 = t2[1][x + 1], b22 = t2[1][x + 2];

    float* op = g_scratch + OFF_X12 + ((size_t)b * 340 + c) * NP;
    #pragma unroll
    for (int i = 0; i < 16; i++) {
        float c10 = t1[i + 2][x], c11 = t1[i + 2][x + 1], c12 = t1[i + 2][x + 2];
        float c20 = t2[i + 2][x], c21 = t2[i + 2][x + 1], c22 = t2[i + 2][x + 2];
        float acc1 = u00 * a10 + u01 * a11 + u02 * a12
                   + u10 * b10 + u11 * b11 + u12 * b12
                   + u20 * c10 + u21 * c11 + u22 * c12;
        float acc2 = v00 * a20 + v01 * a21 + v02 * a22
                   + v10 * b20 + v11 * b21 + v12 * b22
                   + v20 * c20 + v21 * c21 + v22 * c22;
        float r1 = tanhf(acc1) + b11;
        float r2 = tanhf(acc2) + b21;
        op[(r0 + i) * 128 + x] = r1 * r2;
        a10 = b10; a11 = b11; a12 = b12; b10 = c10; b11 = c11; b12 = c12;
        a20 = b20; a21 = b21; a22 = b22; b20 = c20; b21 = c21; b22 = c22;
    }
}

// ============================================================================
extern "C" void kernel_launch(void* const* d_in, const int* in_sizes, int n_in,
                              void* d_out, int out_size)
{
    const float* x      = (const float*)d_in[0];
    const float* y      = (const float*)d_in[1];
    const float* ln_w   = (const float*)d_in[2];
    const float* ln_b   = (const float*)d_in[3];
    const float* temp   = (const float*)d_in[4];
    const float* q_w    = (const float*)d_in[5];
    const float* qdw_w  = (const float*)d_in[6];
    const float* kv_w   = (const float*)d_in[7];
    const float* kvdw_w = (const float*)d_in[8];
    const float* po_w   = (const float*)d_in[9];
    const float* g1_w   = (const float*)d_in[10];
    const float* g1_b   = (const float*)d_in[11];
    const float* g2_w   = (const float*)d_in[12];
    const float* g2_b   = (const float*)d_in[13];
    const float* pin_w  = (const float*)d_in[14];
    const float* dw_w   = (const float*)d_in[15];
    const float* dw1_w  = (const float*)d_in[16];
    const float* dw2_w  = (const float*)d_in[17];
    const float* pout_w = (const float*)d_in[18];
    float* out = (float*)d_out;

    dim3 lnGrid(NP / 256, BB);
    ln_kernel<<<lnGrid, 256>>>(x, 0, OFF_XN, ln_w, ln_b);
    ln_kernel<<<lnGrid, 256>>>(y, 0, OFF_YN, ln_w, ln_b);

    // SCAB branch (tf32 tensor-core GEMMs)
    dim3 gg128(NP / 128, 1, BB);
    gemm_tf32<<<gg128, 256>>>(q_w, OFF_XN, nullptr, OFF_B1, 128, 128, nullptr, 0, 0);
    dwconv_tiled<<<dim3(BB * 128, 8), 128>>>(OFF_B1, OFF_Q, qdw_w, 128);

    dim3 gg256(NP / 128, 2, BB);
    gemm_tf32<<<gg256, 256>>>(kv_w, OFF_YN, nullptr, OFF_KVP, 256, 128, nullptr, 0, 0);
    dwconv_tiled<<<dim3(BB * 256, 8), 128>>>(OFF_KVP, OFF_KV, kvdw_w, 256);

    dim3 cs(128, BB);
    chan_sumsq<<<cs, 256>>>(OFF_Q,  OFF_QSS, 128);
    chan_sumsq<<<cs, 256>>>(OFF_KV, OFF_KSS, 256);

    // gate -> dk (fp32 for bit-stable dk)
    gemm1x1<<<gg128, 256>>>(g1_w, OFF_XN, nullptr, OFF_G1, 64, 128, g1_b, 1);
    gate_reduce<<<256, 256>>>(g2_w, g2_b);
    finish_gate<<<1, 256>>>();

    // attention (fp32 — ordering-sensitive top-k)
    qk_partial<<<dim3(64, 8, BB), 256>>>();
    qk_reduce<<<dim3(8, BB), 256>>>(temp);
    mask_softmax<<<2, 256>>>();
    av_kernel<<<dim3(NP / 256, 8, BB), 256>>>();

    // xatt = x + conv1x1(out, po_w)
    gemm_tf32<<<gg128, 256>>>(po_w, OFF_OUT, nullptr, OFF_XATT, 128, 128, x, 0, 1);

    // IEL branch
    ln_kernel<<<lnGrid, 256>>>(nullptr, OFF_XATT, OFF_YN, ln_w, ln_b);
    dim3 gg680(NP / 128, 6, BB);
    gemm_tf32<<<gg680, 256>>>(pin_w, OFF_YN, nullptr, OFF_TPRE, 680, 128, nullptr, 0, 0);
    dwconv_tiled<<<dim3(BB * 680, 8), 128>>>(OFF_TPRE, OFF_T, dw_w, 680);
    iel_tiled<<<dim3(BB * 340, 8), 128>>>(dw1_w, dw2_w);

    // final: out = conv1x1(x12, pout_w) + xatt
    gemm_tf32<<<gg128, 256>>>(pout_w, OFF_X12, out, 0, 128, 340, nullptr, OFF_XATT, 2);
}

// round 5
// speedup vs baseline: 3.7830x; 1.0002x over previous
#include <cuda_runtime.h>
#include <math.h>

#define NP 16384
#define BB 4

static constexpr size_t F1 = (size_t)BB * 128 * NP;  // 8,388,608 floats

static constexpr size_t OFF_XN   = 0;
static constexpr size_t OFF_YN   = F1;        // reused for z = ln(xatt) later
static constexpr size_t OFF_B1   = 2 * F1;    // q pre-dw
static constexpr size_t OFF_Q    = 3 * F1;
static constexpr size_t OFF_KVP  = 4 * F1;    // 2*F1
static constexpr size_t OFF_KV   = 6 * F1;    // 2*F1
static constexpr size_t OFF_WEFF = 8 * F1;    // per-batch composed po@attn weights (4*16384)
static constexpr size_t OFF_XATT = 9 * F1;
static constexpr size_t OFF_TPRE = 10 * F1;                       // 680ch
static constexpr size_t OFF_T    = OFF_TPRE + (size_t)BB*680*NP;  // (unused now)
static constexpr size_t OFF_X12  = OFF_T    + (size_t)BB*680*NP;  // 340ch
static constexpr size_t OFF_G1   = OFF_X12  + (size_t)BB*340*NP;  // 64ch
static constexpr size_t OFF_ATTN = OFF_G1   + (size_t)BB*64*NP;   // 4*8*16*16
static constexpr size_t OFF_QSS  = OFF_ATTN + 8192;               // 512
static constexpr size_t OFF_KSS  = OFF_QSS  + 512;                // 512
static constexpr size_t OFF_PART = OFF_KSS  + 512;                // 256 partials
static constexpr size_t OFF_QKP  = OFF_PART + 256;                // 32*64*256 qk partials
static constexpr size_t OFF_SSQP_Q  = OFF_QKP + (size_t)32 * 64 * 256;  // 512*8
static constexpr size_t OFF_SSQP_KV = OFF_SSQP_Q + 4096;                // 1024*8
static constexpr size_t SCRATCH_TOTAL = OFF_SSQP_KV + 8192;

__device__ float g_scratch[SCRATCH_TOTAL];
__device__ int   g_dk;

__device__ __forceinline__ unsigned f2tf32(float f) {
    unsigned r;
    asm("cvt.rna.tf32.f32 %0, %1;" : "=r"(r) : "f"(f));
    return r;
}

// ---------------- LayerNorm over channel axis (C=128), NCHW ----------------
__global__ void ln_kernel(const float* __restrict__ in_ptr, size_t in_off, size_t out_off,
                          const float* __restrict__ w, const float* __restrict__ bp)
{
    int p = blockIdx.x * blockDim.x + threadIdx.x;   // pixel within batch
    int b = blockIdx.y;
    const float* ip = (in_ptr ? in_ptr : g_scratch + in_off) + (size_t)b * 128 * NP + p;
    float s = 0.f, ss = 0.f;
    #pragma unroll 8
    for (int c = 0; c < 128; c++) { float v = ip[(size_t)c * NP]; s += v; ss += v * v; }
    float mu  = s * (1.f / 128.f);
    float var = ss * (1.f / 128.f) - mu * mu;
    float inv = rsqrtf(var + 1e-6f);
    float* op = g_scratch + out_off + (size_t)b * 128 * NP + p;
    #pragma unroll 8
    for (int c = 0; c < 128; c++) {
        float v = ip[(size_t)c * NP];
        op[(size_t)c * NP] = w[c] * ((v - mu) * inv) + bp[c];
    }
}

// ---------------- tf32 tensor-core GEMM: out[M,NP] = W[M,K] @ in[K,NP] --------
// W source: if Wp!=null use Wp + b*wstride, else g_scratch + w_off + b*wstride.
// in = g_scratch + in_off + b*in_cs*NP.
// rflag: 0 none, 1 residual from resid_ptr, 2 residual from scratch+resid_off
__global__ __launch_bounds__(256, 2)
void gemm_tf32(const float* __restrict__ Wp, size_t w_off, size_t wstride,
               size_t in_off, int in_cs,
               float* __restrict__ out_ptr, size_t out_off,
               int M, int K,
               const float* __restrict__ resid_ptr, size_t resid_off, int rflag)
{
    __shared__ unsigned As[32][136];   // [k][m] tf32 bits
    __shared__ unsigned Bs[32][136];   // [k][n] tf32 bits

    int b = blockIdx.z;
    const float* W = (Wp ? Wp : (const float*)(g_scratch + w_off)) + (size_t)b * wstride;
    const float* in = g_scratch + in_off + (size_t)b * in_cs * NP;
    float* out = (out_ptr ? out_ptr : g_scratch + out_off) + (size_t)b * M * NP;
    const float* res = nullptr;
    if (rflag == 1)      res = resid_ptr + (size_t)b * M * NP;
    else if (rflag == 2) res = g_scratch + resid_off + (size_t)b * M * NP;

    int m0 = blockIdx.y * 128, n0 = blockIdx.x * 128;
    int t = threadIdx.x;
    int lane = t & 31, wid = t >> 5;
    int wm = (wid & 1) * 64;        // warp m offset in tile
    int wn = (wid >> 1) * 32;       // warp n offset in tile
    int gid = lane >> 2, tig = lane & 3;

    float acc[4][4][4];
    #pragma unroll
    for (int i = 0; i < 4; i++)
        #pragma unroll
        for (int j = 0; j < 4; j++)
            #pragma unroll
            for (int r = 0; r < 4; r++) acc[i][j][r] = 0.f;

    int KT = (K + 31) >> 5;
    for (int kt = 0; kt < KT; kt++) {
        int k0 = kt << 5;
        // ---- load A tile: As[k][m] <- W[m0+m][k0+k], tf32 ----
        #pragma unroll
        for (int i = 0; i < 4; i++) {
            int lin = t + i * 256;            // 0..1023
            int m = lin >> 3, kq = lin & 7;   // m 0..127, kq 0..7 (4 k each)
            int gm = m0 + m, gk = k0 + kq * 4;
            float v0 = 0.f, v1 = 0.f, v2 = 0.f, v3 = 0.f;
            if (gm < M) {
                if (gk + 3 < K) {
                    float4 w4 = *(const float4*)&W[(size_t)gm * K + gk];
                    v0 = w4.x; v1 = w4.y; v2 = w4.z; v3 = w4.w;
                } else {
                    if (gk + 0 < K) v0 = W[(size_t)gm * K + gk + 0];
                    if (gk + 1 < K) v1 = W[(size_t)gm * K + gk + 1];
                    if (gk + 2 < K) v2 = W[(size_t)gm * K + gk + 2];
                    if (gk + 3 < K) v3 = W[(size_t)gm * K + gk + 3];
                }
            }
            As[kq * 4 + 0][m] = f2tf32(v0);
            As[kq * 4 + 1][m] = f2tf32(v1);
            As[kq * 4 + 2][m] = f2tf32(v2);
            As[kq * 4 + 3][m] = f2tf32(v3);
        }
        // ---- load B tile: Bs[k][n] <- in[k0+k][n0+n], tf32 ----
        #pragma unroll
        for (int i = 0; i < 4; i++) {
            int lin = t + i * 256;            // 0..1023
            int kk = lin >> 5, nq = lin & 31; // kk 0..31, nq 0..31 (4 n each)
            unsigned u0 = 0, u1 = 0, u2 = 0, u3 = 0;
            if (k0 + kk < K) {
                float4 v4 = *(const float4*)&in[(size_t)(k0 + kk) * NP + n0 + nq * 4];
                u0 = f2tf32(v4.x); u1 = f2tf32(v4.y); u2 = f2tf32(v4.z); u3 = f2tf32(v4.w);
            }
            Bs[kk][nq * 4 + 0] = u0;
            Bs[kk][nq * 4 + 1] = u1;
            Bs[kk][nq * 4 + 2] = u2;
            Bs[kk][nq * 4 + 3] = u3;
        }
        __syncthreads();

        #pragma unroll
        for (int ks = 0; ks < 4; ks++) {
            int kb = ks * 8;
            unsigned af[4][4], bf[4][2];
            #pragma unroll
            for (int mi = 0; mi < 4; mi++) {
                int rlo = wm + mi * 16 + gid;
                af[mi][0] = As[kb + tig][rlo];
                af[mi][1] = As[kb + tig][rlo + 8];
                af[mi][2] = As[kb + tig + 4][rlo];
                af[mi][3] = As[kb + tig + 4][rlo + 8];
            }
            #pragma unroll
            for (int ni = 0; ni < 4; ni++) {
                int col = wn + ni * 8 + gid;
                bf[ni][0] = Bs[kb + tig][col];
                bf[ni][1] = Bs[kb + tig + 4][col];
            }
            #pragma unroll
            for (int mi = 0; mi < 4; mi++)
                #pragma unroll
                for (int ni = 0; ni < 4; ni++) {
                    asm volatile(
                        "mma.sync.aligned.m16n8k8.row.col.f32.tf32.tf32.f32 "
                        "{%0,%1,%2,%3}, {%4,%5,%6,%7}, {%8,%9}, {%0,%1,%2,%3};"
                        : "+f"(acc[mi][ni][0]), "+f"(acc[mi][ni][1]),
                          "+f"(acc[mi][ni][2]), "+f"(acc[mi][ni][3])
                        : "r"(af[mi][0]), "r"(af[mi][1]), "r"(af[mi][2]), "r"(af[mi][3]),
                          "r"(bf[ni][0]), "r"(bf[ni][1]));
                }
        }
        __syncthreads();
    }

    // ---- epilogue ----
    #pragma unroll
    for (int mi = 0; mi < 4; mi++) {
        int row0 = m0 + wm + mi * 16 + gid;
        int row1 = row0 + 8;
        #pragma unroll
        for (int ni = 0; ni < 4; ni++) {
            int col = n0 + wn + ni * 8 + tig * 2;
            if (row0 < M) {
                float2 v = make_float2(acc[mi][ni][0], acc[mi][ni][1]);
                if (res) {
                    float2 r = *(const float2*)&res[(size_t)row0 * NP + col];
                    v.x += r.x; v.y += r.y;
                }
                *(float2*)&out[(size_t)row0 * NP + col] = v;
            }
            if (row1 < M) {
                float2 v = make_float2(acc[mi][ni][2], acc[mi][ni][3]);
                if (res) {
                    float2 r = *(const float2*)&res[(size_t)row1 * NP + col];
                    v.x += r.x; v.y += r.y;
                }
                *(float2*)&out[(size_t)row1 * NP + col] = v;
            }
        }
    }
}

// ---------------- fp32 GEMM (gate path only — dk must stay bit-stable) -------
__global__ __launch_bounds__(256, 2)
void gemm1x1(const float* __restrict__ W, size_t in_off,
             float* __restrict__ out_ptr, size_t out_off,
             int M, int K,
             const float* __restrict__ bias, int do_relu)
{
    __shared__ float As[16][132];
    __shared__ float Bs[16][132];
    int b = blockIdx.z;
    const float* in = g_scratch + in_off + (size_t)b * K * NP;
    float* out = (out_ptr ? out_ptr : g_scratch + out_off) + (size_t)b * M * NP;

    int m0 = blockIdx.y * 128, n0 = blockIdx.x * 128;
    int t = threadIdx.x;
    int tx = t & 15, ty = t >> 4;
    float acc[8][8] = {};

    int KT = (K + 15) >> 4;
    for (int kt = 0; kt < KT; kt++) {
        int k0 = kt << 4;
        #pragma unroll
        for (int i = 0; i < 2; i++) {
            int idx = t * 2 + i;
            int row = idx >> 2, seg = idx & 3;
            int m = m0 + row, k = k0 + seg * 4;
            float4 w4 = make_float4(0.f, 0.f, 0.f, 0.f);
            if (m < M && k < K) w4 = *(const float4*)&W[(size_t)m * K + k];
            As[seg * 4 + 0][row] = w4.x;
            As[seg * 4 + 1][row] = w4.y;
            As[seg * 4 + 2][row] = w4.z;
            As[seg * 4 + 3][row] = w4.w;
        }
        #pragma unroll
        for (int i = 0; i < 2; i++) {
            int idx = t * 2 + i;
            int kk = idx >> 5, seg = idx & 31;
            float4 v4 = make_float4(0.f, 0.f, 0.f, 0.f);
            if (k0 + kk < K) v4 = *(const float4*)&in[(size_t)(k0 + kk) * NP + n0 + seg * 4];
            *(float4*)&Bs[kk][seg * 4] = v4;
        }
        __syncthreads();
        #pragma unroll
        for (int kk = 0; kk < 16; kk++) {
            float4 a0 = *(float4*)&As[kk][ty * 8];
            float4 a1 = *(float4*)&As[kk][ty * 8 + 4];
            float4 b0 = *(float4*)&Bs[kk][tx * 8];
            float4 b1 = *(float4*)&Bs[kk][tx * 8 + 4];
            float a[8] = {a0.x, a0.y, a0.z, a0.w, a1.x, a1.y, a1.z, a1.w};
            float bbv[8] = {b0.x, b0.y, b0.z, b0.w, b1.x, b1.y, b1.z, b1.w};
            #pragma unroll
            for (int i = 0; i < 8; i++)
                #pragma unroll
                for (int j = 0; j < 8; j++)
                    acc[i][j] += a[i] * bbv[j];
        }
        __syncthreads();
    }

    #pragma unroll
    for (int i = 0; i < 8; i++) {
        int m = m0 + ty * 8 + i;
        if (m >= M) break;
        float bv = bias ? bias[m] : 0.f;
        size_t rowoff = (size_t)m * NP + n0 + tx * 8;
        float v[8];
        #pragma unroll
        for (int j = 0; j < 8; j++) {
            v[j] = acc[i][j] + bv;
            if (do_relu) v[j] = fmaxf(v[j], 0.f);
        }
        *(float4*)&out[rowoff]     = make_float4(v[0], v[1], v[2], v[3]);
        *(float4*)&out[rowoff + 4] = make_float4(v[4], v[5], v[6], v[7]);
    }
}

// ---------------- tiled depthwise 3x3, pad=1, with sumsq partials ------------
__global__ void dwconv_tiled(size_t in_off, size_t out_off, const float* __restrict__ wts,
                             int C, size_t ssq_off)
{
    __shared__ float tile[18][130];
    __shared__ float red[128];
    int plane = blockIdx.x;                 // b*C + c
    int c = plane % C;
    int r0 = blockIdx.y * 16;
    int x = threadIdx.x;                    // 0..127
    const float* ip = g_scratch + in_off + (size_t)plane * NP;
    float* op = g_scratch + out_off + (size_t)plane * NP;

    #pragma unroll
    for (int i = 0; i < 18; i++) {
        int y = r0 - 1 + i;
        tile[i][x + 1] = ((unsigned)y < 128u) ? ip[y * 128 + x] : 0.f;
    }
    if (x < 18) { tile[x][0] = 0.f; tile[x][129] = 0.f; }
    __syncthreads();

    const float* kp = wts + c * 9;
    float w00 = kp[0], w01 = kp[1], w02 = kp[2];
    float w10 = kp[3], w11 = kp[4], w12 = kp[5];
    float w20 = kp[6], w21 = kp[7], w22 = kp[8];

    float a0 = tile[0][x], a1 = tile[0][x + 1], a2 = tile[0][x + 2];
    float b0 = tile[1][x], b1 = tile[1][x + 1], b2 = tile[1][x + 2];
    float ssq = 0.f;
    #pragma unroll
    for (int i = 0; i < 16; i++) {
        float c0 = tile[i + 2][x], c1 = tile[i + 2][x + 1], c2 = tile[i + 2][x + 2];
        float acc = w00 * a0 + w01 * a1 + w02 * a2
                  + w10 * b0 + w11 * b1 + w12 * b2
                  + w20 * c0 + w21 * c1 + w22 * c2;
        op[(r0 + i) * 128 + x] = acc;
        ssq += acc * acc;
        a0 = b0; a1 = b1; a2 = b2;
        b0 = c0; b1 = c1; b2 = c2;
    }
    red[x] = ssq; __syncthreads();
    for (int st = 64; st; st >>= 1) {
        if (x < st) red[x] += red[x + st];
        __syncthreads();
    }
    if (!x) g_scratch[ssq_off + (size_t)plane * 8 + blockIdx.y] = red[0];
}

// ---------------- reduce 8 sumsq partials per channel ----------------
// out[b*128+c] = sum_r part[(b*in_cs + c)*8 + r]   (c in [0,128))
__global__ void ssq_reduce(size_t part_off, size_t out_off, int in_cs)
{
    int idx = blockIdx.x * blockDim.x + threadIdx.x;   // 0..511
    if (idx >= 512) return;
    int b = idx >> 7, c = idx & 127;
    const float* p = g_scratch + part_off + ((size_t)b * in_cs + c) * 8;
    float s = 0.f;
    #pragma unroll
    for (int r = 0; r < 8; r++) s += p[r];
    g_scratch[out_off + idx] = s;
}

// ---------------- qk partials: 16x16 over a 256-px chunk per block ------------
__global__ void qk_partial()
{
    __shared__ float qs[16][257];
    __shared__ float ks[16][257];
    int chunk = blockIdx.x, h = blockIdx.y, b = blockIdx.z;
    int n0 = chunk * 256;
    int t = threadIdx.x;
    const float* qbase = g_scratch + OFF_Q  + ((size_t)b * 128 + h * 16) * NP + n0;
    const float* kbase = g_scratch + OFF_KV + ((size_t)b * 256 + h * 16) * NP + n0;
    #pragma unroll
    for (int r = 0; r < 16; r++) {
        qs[r][t] = qbase[(size_t)r * NP + t];
        ks[r][t] = kbase[(size_t)r * NP + t];
    }
    __syncthreads();
    int c = t >> 4, d = t & 15;
    float acc = 0.f;
    #pragma unroll 8
    for (int n = 0; n < 256; n++) acc += qs[c][n] * ks[d][n];
    g_scratch[OFF_QKP + (((size_t)(b * 8 + h) * 64 + chunk) * 256) + t] = acc;
}

// ---------------- qk reduce + normalize + temperature -------------------------
__global__ void qk_reduce(const float* __restrict__ temp)
{
    int h = blockIdx.x, b = blockIdx.y;
    int t = threadIdx.x;
    float acc = 0.f;
    const float* p = g_scratch + OFF_QKP + (size_t)(b * 8 + h) * 64 * 256 + t;
    #pragma unroll 8
    for (int j = 0; j < 64; j++) acc += p[j * 256];
    int c = t >> 4, d = t & 15;
    float qn = fmaxf(sqrtf(g_scratch[OFF_QSS + b * 128 + h * 16 + c]), 1e-12f);
    float kn = fmaxf(sqrtf(g_scratch[OFF_KSS + b * 128 + h * 16 + d]), 1e-12f);
    g_scratch[OFF_ATTN + (size_t)(b * 8 + h) * 256 + t] = acc / (qn * kn) * temp[h];
}

// ---------------- dynamic top-k mask + softmax --------------------------------
__global__ void mask_softmax()
{
    int r = blockIdx.x * blockDim.x + threadIdx.x;   // 512 rows total
    if (r >= BB * 8 * 16) return;
    float* row = g_scratch + OFF_ATTN + (size_t)r * 16;
    int dk = g_dk;
    float vals[16];
    #pragma unroll
    for (int i = 0; i < 16; i++) vals[i] = row[i];
    float mx = -3.4e38f;
    bool keep[16];
    #pragma unroll
    for (int i = 0; i < 16; i++) {
        int rank = 0;
        #pragma unroll
        for (int j = 0; j < 16; j++)
            rank += (vals[j] > vals[i]) || (vals[j] == vals[i] && j < i);
        keep[i] = rank < dk;
        if (keep[i] && vals[i] > mx) mx = vals[i];
    }
    float sum = 0.f, e[16];
    #pragma unroll
    for (int i = 0; i < 16; i++) { e[i] = keep[i] ? expf(vals[i] - mx) : 0.f; sum += e[i]; }
    float isum = 1.f / sum;
    #pragma unroll
    for (int i = 0; i < 16; i++) row[i] = e[i] * isum;
}

// ---------------- W_eff[b] = po_w @ blockdiag(attn_b) ------------------------
__global__ void compose_weff(const float* __restrict__ po_w)
{
    __shared__ float at[2048];
    int b = blockIdx.x;
    int t = threadIdx.x;                  // 128, thread = output row m
    for (int i = t; i < 2048; i += 128) at[i] = g_scratch[OFF_ATTN + (size_t)b * 2048 + i];
    __syncthreads();
    int m = t;
    float* wo = g_scratch + OFF_WEFF + ((size_t)b * 128 + m) * 128;
    #pragma unroll
    for (int h = 0; h < 8; h++) {
        float pw[16];
        #pragma unroll
        for (int c = 0; c < 16; c++) pw[c] = po_w[(size_t)m * 128 + h * 16 + c];
        #pragma unroll
        for (int d = 0; d < 16; d++) {
            float acc = 0.f;
            #pragma unroll
            for (int c = 0; c < 16; c++) acc += pw[c] * at[h * 256 + c * 16 + d];
            wo[h * 16 + d] = acc;
        }
    }
}

// ---------------- gate: g2 conv + sigmoid + deterministic partial sums --------
__global__ void gate_reduce(const float* __restrict__ g2w, const float* __restrict__ g2b)
{
    int p = blockIdx.x * blockDim.x + threadIdx.x;   // 0..65535
    int b = p / NP, pp = p % NP;
    const float* base = g_scratch + OFF_G1 + ((size_t)b * 64) * NP + pp;
    float s = g2b[0];
    #pragma unroll 8
    for (int c = 0; c < 64; c++) s += g2w[c] * base[(size_t)c * NP];
    float v = 1.f / (1.f + expf(-s));
    __shared__ float red[256];
    red[threadIdx.x] = v; __syncthreads();
    for (int st = 128; st; st >>= 1) {
        if (threadIdx.x < st) red[threadIdx.x] += red[threadIdx.x + st];
        __syncthreads();
    }
    if (!threadIdx.x) g_scratch[OFF_PART + blockIdx.x] = red[0];
}

__global__ void finish_gate()
{
    __shared__ float red[256];
    red[threadIdx.x] = g_scratch[OFF_PART + threadIdx.x];
    __syncthreads();
    for (int st = 128; st; st >>= 1) {
        if (threadIdx.x < st) red[threadIdx.x] += red[threadIdx.x + st];
        __syncthreads();
    }
    if (!threadIdx.x) {
        float mean = red[0] * (1.f / 65536.f);
        int dk = (int)(16.f * mean);               // trunc like astype(int32)
        g_dk = dk < 1 ? 1 : (dk > 16 ? 16 : dk);
    }
}

// ---------------- fully fused IEL tail ----------------------------------------
// Reads TPRE (pre-dw), computes x1 = dw(TPRE_c), x2 = dw(TPRE_{340+c}) in smem,
// then x12 = (tanh(dw1(x1)) + x1) * (tanh(dw2(x2)) + x2).
// 8-row output strip; raw halo is 12x132 (±2), x-tile 10x130 (±1).
__global__ void iel_fused(const float* __restrict__ dw_w,
                          const float* __restrict__ w1, const float* __restrict__ w2)
{
    __shared__ float raw1[12][132], raw2[12][132];
    __shared__ float t1[10][130], t2[10][130];
    int pid = blockIdx.x;                  // b*340 + c
    int b = pid / 340, c = pid % 340;
    int r0 = blockIdx.y * 8;
    int x = threadIdx.x;                   // 0..127
    const float* p1 = g_scratch + OFF_TPRE + ((size_t)b * 680 + c) * NP;
    const float* p2 = p1 + (size_t)340 * NP;

    // load raw halo: rows r0-2..r0+9, smem col j holds actual col j-2
    #pragma unroll
    for (int i = 0; i < 12; i++) {
        int y = r0 - 2 + i;
        bool yok = (unsigned)y < 128u;
        int ac = x - 2;
        bool cok = (unsigned)ac < 128u;
        raw1[i][x] = (yok && cok) ? p1[y * 128 + ac] : 0.f;
        raw2[i][x] = (yok && cok) ? p2[y * 128 + ac] : 0.f;
        if (x < 4) {
            int ac2 = 126 + x;
            bool c2ok = ac2 < 128;
            raw1[i][128 + x] = (yok && c2ok) ? p1[y * 128 + ac2] : 0.f;
            raw2[i][128 + x] = (yok && c2ok) ? p2[y * 128 + ac2] : 0.f;
        }
    }
    __syncthreads();

    const float* kd1 = dw_w + (size_t)c * 9;
    const float* kd2 = dw_w + (size_t)(340 + c) * 9;
    float d10 = kd1[0], d11 = kd1[1], d12 = kd1[2], d13 = kd1[3], d14 = kd1[4],
          d15 = kd1[5], d16 = kd1[6], d17 = kd1[7], d18 = kd1[8];
    float e10 = kd2[0], e11 = kd2[1], e12 = kd2[2], e13 = kd2[3], e14 = kd2[4],
          e15 = kd2[5], e16 = kd2[6], e17 = kd2[7], e18 = kd2[8];

    // stage 2: x tiles. thread x computes col j = x+1 (actual col x) for rows 0..9
    {
        int j = x + 1;
        #pragma unroll
        for (int i = 0; i < 10; i++) {
            int yv = r0 - 1 + i;
            bool yok = (unsigned)yv < 128u;
            float v1 = 0.f, v2 = 0.f;
            if (yok) {
                v1 = d10 * raw1[i][j]     + d11 * raw1[i][j + 1]     + d12 * raw1[i][j + 2]
                   + d13 * raw1[i + 1][j] + d14 * raw1[i + 1][j + 1] + d15 * raw1[i + 1][j + 2]
                   + d16 * raw1[i + 2][j] + d17 * raw1[i + 2][j + 1] + d18 * raw1[i + 2][j + 2];
                v2 = e10 * raw2[i][j]     + e11 * raw2[i][j + 1]     + e12 * raw2[i][j + 2]
                   + e13 * raw2[i + 1][j] + e14 * raw2[i + 1][j + 1] + e15 * raw2[i + 1][j + 2]
                   + e16 * raw2[i + 2][j] + e17 * raw2[i + 2][j + 1] + e18 * raw2[i + 2][j + 2];
            }
            t1[i][j] = v1;
            t2[i][j] = v2;
        }
        if (x < 10) { t1[x][0] = 0.f; t1[x][129] = 0.f; t2[x][0] = 0.f; t2[x][129] = 0.f; }
    }
    __syncthreads();

    const float* k1 = w1 + (size_t)c * 9;
    const float* k2 = w2 + (size_t)c * 9;
    float u00 = k1[0], u01 = k1[1], u02 = k1[2], u10 = k1[3], u11 = k1[4],
          u12 = k1[5], u20 = k1[6], u21 = k1[7], u22 = k1[8];
    float v00 = k2[0], v01 = k2[1], v02 = k2[2], v10 = k2[3], v11 = k2[4],
          v12 = k2[5], v20 = k2[6], v21 = k2[7], v22 = k2[8];

    float* op = g_scratch + OFF_X12 + ((size_t)b * 340 + c) * NP;
    #pragma unroll
    for (int i = 0; i < 8; i++) {
        float acc1 = u00 * t1[i][x]     + u01 * t1[i][x + 1]     + u02 * t1[i][x + 2]
                   + u10 * t1[i + 1][x] + u11 * t1[i + 1][x + 1] + u12 * t1[i + 1][x + 2]
                   + u20 * t1[i + 2][x] + u21 * t1[i + 2][x + 1] + u22 * t1[i + 2][x + 2];
        float acc2 = v00 * t2[i][x]     + v01 * t2[i][x + 1]     + v02 * t2[i][x + 2]
                   + v10 * t2[i + 1][x] + v11 * t2[i + 1][x + 1] + v12 * t2[i + 1][x + 2]
                   + v20 * t2[i + 2][x] + v21 * t2[i + 2][x + 1] + v22 * t2[i + 2][x + 2];
        float r1 = tanhf(acc1) + t1[i + 1][x + 1];
        float r2 = tanhf(acc2) + t2[i + 1][x + 1];
        op[(r0 + i) * 128 + x] = r1 * r2;
    }
}

// ============================================================================
extern "C" void kernel_launch(void* const* d_in, const int* in_sizes, int n_in,
                              void* d_out, int out_size)
{
    const float* x      = (const float*)d_in[0];
    const float* y      = (const float*)d_in[1];
    const float* ln_w   = (const float*)d_in[2];
    const float* ln_b   = (const float*)d_in[3];
    const float* temp   = (const float*)d_in[4];
    const float* q_w    = (const float*)d_in[5];
    const float* qdw_w  = (const float*)d_in[6];
    const float* kv_w   = (const float*)d_in[7];
    const float* kvdw_w = (const float*)d_in[8];
    const float* po_w   = (const float*)d_in[9];
    const float* g1_w   = (const float*)d_in[10];
    const float* g1_b   = (const float*)d_in[11];
    const float* g2_w   = (const float*)d_in[12];
    const float* g2_b   = (const float*)d_in[13];
    const float* pin_w  = (const float*)d_in[14];
    const float* dw_w   = (const float*)d_in[15];
    const float* dw1_w  = (const float*)d_in[16];
    const float* dw2_w  = (const float*)d_in[17];
    const float* pout_w = (const float*)d_in[18];
    float* out = (float*)d_out;

    dim3 lnGrid(NP / 256, BB);
    ln_kernel<<<lnGrid, 256>>>(x, 0, OFF_XN, ln_w, ln_b);
    ln_kernel<<<lnGrid, 256>>>(y, 0, OFF_YN, ln_w, ln_b);

    // SCAB branch (tf32 tensor-core GEMMs)
    dim3 gg128(NP / 128, 1, BB);
    gemm_tf32<<<gg128, 256>>>(q_w, 0, 0, OFF_XN, 128, nullptr, OFF_B1, 128, 128, nullptr, 0, 0);
    dwconv_tiled<<<dim3(BB * 128, 8), 128>>>(OFF_B1, OFF_Q, qdw_w, 128, OFF_SSQP_Q);

    dim3 gg256(NP / 128, 2, BB);
    gemm_tf32<<<gg256, 256>>>(kv_w, 0, 0, OFF_YN, 128, nullptr, OFF_KVP, 256, 128, nullptr, 0, 0);
    dwconv_tiled<<<dim3(BB * 256, 8), 128>>>(OFF_KVP, OFF_KV, kvdw_w, 256, OFF_SSQP_KV);

    ssq_reduce<<<2, 256>>>(OFF_SSQP_Q,  OFF_QSS, 128);
    ssq_reduce<<<2, 256>>>(OFF_SSQP_KV, OFF_KSS, 256);

    // gate -> dk (fp32 for bit-stable dk)
    gemm1x1<<<gg128, 256>>>(g1_w, OFF_XN, nullptr, OFF_G1, 64, 128, g1_b, 1);
    gate_reduce<<<256, 256>>>(g2_w, g2_b);
    finish_gate<<<1, 256>>>();

    // attention logits (fp32 — ordering-sensitive top-k)
    qk_partial<<<dim3(64, 8, BB), 256>>>();
    qk_reduce<<<dim3(8, BB), 256>>>(temp);
    mask_softmax<<<2, 256>>>();

    // fold attn into po: W_eff[b] = po_w @ blockdiag(attn_b); xatt = x + W_eff @ v
    compose_weff<<<BB, 128>>>(po_w);
    gemm_tf32<<<gg128, 256>>>(nullptr, OFF_WEFF, 16384,
                              OFF_KV + (size_t)128 * NP, 256,
                              nullptr, OFF_XATT, 128, 128, x, 0, 1);

    // IEL branch
    ln_kernel<<<lnGrid, 256>>>(nullptr, OFF_XATT, OFF_YN, ln_w, ln_b);
    dim3 gg680(NP / 128, 6, BB);
    gemm_tf32<<<gg680, 256>>>(pin_w, 0, 0, OFF_YN, 128, nullptr, OFF_TPRE, 680, 128, nullptr, 0, 0);
    iel_fused<<<dim3(BB * 340, 16), 128>>>(dw_w, dw1_w, dw2_w);

    // final: out = conv1x1(x12, pout_w) + xatt
    gemm_tf32<<<gg128, 256>>>(pout_w, 0, 0, OFF_X12, 340, out, 0, 128, 340, nullptr, OFF_XATT, 2);
}